// round 11
// baseline (speedup 1.0000x reference)
#include <cuda_runtime.h>
#include <cuda_bf16.h>
#include <math.h>
#include <stdint.h>

// Problem constants (fixed shapes per reference)
#define NN    50000
#define NF    2000
#define KPAD  2048
#define D1    64
#define HEADS 8
#define HID   8
#define NC    30
#define NCP   32
#define MAXET 1700000

// ---------------- scratch (device globals; no allocation allowed) ----------
__device__ float g_h1[(size_t)NN * D1];
__device__ float g_res[(size_t)NN * D1];
__device__ float g_as1[NN * HEADS];
__device__ float g_ad1[NN * HEADS];
__device__ float g_sum1[NN * HEADS];
__device__ float g_out1[(size_t)NN * D1];
__device__ float g_h2[(size_t)NN * NCP];
__device__ float g_as2[NN];
__device__ float g_ad2[NN];
__device__ float g_sum2[NN];
__device__ float g_out2[(size_t)NN * NCP];
// pre-transposed + split weights: [n=0..127][k=0..2047] bf16 (zeros past NF)
__device__ unsigned short g_wt_hi[128 * KPAD];
__device__ unsigned short g_wt_lo[128 * KPAD];

// ---------------- helpers ----------------
__device__ __forceinline__ void edge_sd(const int* __restrict__ ei, int E, int e,
                                        int& s, int& d) {
    if (e < E) { s = ei[e]; d = ei[E + e]; }
    else       { s = e - E; d = e - E; }
}
__device__ __forceinline__ void red_add_v4(float* addr, float a, float b, float c, float d) {
    asm volatile("red.global.add.v4.f32 [%0], {%1,%2,%3,%4};"
                 :: "l"(addr), "f"(a), "f"(b), "f"(c), "f"(d) : "memory");
}
__device__ __forceinline__ void red_add_v2(float* addr, float a, float b) {
    asm volatile("red.global.add.v2.f32 [%0], {%1,%2};"
                 :: "l"(addr), "f"(a), "f"(b) : "memory");
}
__device__ __forceinline__ uint32_t smem_u32(const void* p) {
    uint32_t a;
    asm("{ .reg .u64 t; cvta.to.shared.u64 t, %1; cvt.u32.u64 %0, t; }" : "=r"(a) : "l"(p));
    return a;
}
// pack two floats -> bf16x2: first arg to UPPER half, second to LOWER half
__device__ __forceinline__ uint32_t pack_bf16x2(float h, float l) {
    uint32_t r;
    asm("cvt.rn.bf16x2.f32 %0, %1, %2;" : "=r"(r) : "f"(h), "f"(l));
    return r;
}
__device__ __forceinline__ void ldsm4(uint32_t& r0, uint32_t& r1, uint32_t& r2,
                                      uint32_t& r3, uint32_t addr) {
    asm volatile("ldmatrix.sync.aligned.m8n8.x4.shared.b16 {%0,%1,%2,%3}, [%4];"
                 : "=r"(r0), "=r"(r1), "=r"(r2), "=r"(r3) : "r"(addr));
}
__device__ __forceinline__ void mma16816(float* d, uint32_t a0, uint32_t a1,
                                         uint32_t a2, uint32_t a3,
                                         uint32_t b0, uint32_t b1) {
    asm volatile("mma.sync.aligned.m16n8k16.row.col.f32.bf16.bf16.f32 "
                 "{%0,%1,%2,%3}, {%4,%5,%6,%7}, {%8,%9}, {%0,%1,%2,%3};"
                 : "+f"(d[0]), "+f"(d[1]), "+f"(d[2]), "+f"(d[3])
                 : "r"(a0), "r"(a1), "r"(a2), "r"(a3), "r"(b0), "r"(b1));
}
__device__ __forceinline__ void cp16(uint32_t smaddr, const void* gptr) {
    asm volatile("cp.async.cg.shared.global [%0], [%1], 16;"
                 :: "r"(smaddr), "l"(gptr) : "memory");
}
// split fp32 pair -> bf16x2 (hi = truncation, lo = RN residual)
__device__ __forceinline__ void cvt_split(float2 v, uint32_t& hi, uint32_t& lo) {
    uint32_t vx = __float_as_uint(v.x), vy = __float_as_uint(v.y);
    hi = __byte_perm(vx, vy, 0x7632);      // low half = bf16_trunc(v.x), high = v.y
    float hx = __uint_as_float(vx & 0xFFFF0000u);
    float hy = __uint_as_float(vy & 0xFFFF0000u);
    lo = pack_bf16x2(v.y - hy, v.x - hx);
}

// ---------------- init ----------------
__global__ void k_init_all() {
    int i = blockIdx.x * blockDim.x + threadIdx.x;
    if (i < NN * D1)    g_out1[i] = 0.f;
    if (i < NN * NCP)   g_out2[i] = 0.f;
    if (i < NN * HEADS) g_sum1[i] = 0.f;
    if (i < NN)         g_sum2[i] = 0.f;
}

// ---------------- prep: transpose + bf16-split weights -------------------
__global__ void k_prep_w(const float* __restrict__ w1, const float* __restrict__ wres) {
    int idx = blockIdx.x * blockDim.x + threadIdx.x;
    if (idx >= 128 * KPAD) return;
    int n = idx >> 11;
    int k = idx & (KPAD - 1);
    float v = 0.f;
    if (k < NF) v = (n < 64) ? w1[(size_t)k * 64 + n] : wres[(size_t)k * 64 + (n - 64)];
    __nv_bfloat16 hi = __float2bfloat16(v);
    float rem = v - __bfloat162float(hi);
    __nv_bfloat16 lo = __float2bfloat16(rem);
    g_wt_hi[idx] = __bfloat16_as_ushort(hi);
    g_wt_lo[idx] = __bfloat16_as_ushort(lo);
}

// ---------------- GEMM1 via mma.sync bf16x3 + fused att1 ------------------
// [h1 | res] = x @ [w1 | wres]; as1/ad1 computed in-epilogue via quad shfl.
// 256 threads = 8 warps; warp w owns rows mbase+w*16. BK=32, 63 chunks.
// D = Ahi*Bhi + Ahi*Blo + Alo*Bhi  (bf16x3; rel err ~1e-5)
#define NCH 63

__global__ __launch_bounds__(256, 2) void k_gemm1(const float* __restrict__ x,
                                                  const float* __restrict__ bres,
                                                  const float* __restrict__ asrc,
                                                  const float* __restrict__ adst) {
    __shared__ __align__(1024) unsigned char Bsm[32768]; // HI:0/8192, LO:16384/24576

    const int tid = threadIdx.x, wid = tid >> 5, lane = tid & 31;
    const int g = lane >> 2, c4 = lane & 3;
    const int mbase = blockIdx.x * 128 + wid * 16;
    int r0 = mbase + g;      if (r0 >= NN) r0 = NN - 1;
    int r1 = mbase + g + 8;  if (r1 >= NN) r1 = NN - 1;
    const uint32_t sb = smem_u32(Bsm);

    // ldmatrix per-lane constants
    const int nL   = (lane & 7) | ((lane & 16) >> 1);  // 0..15
    const int cbit = (lane >> 3) & 1;
    const int q    = cbit ^ ((nL >> 1) & 3);
    const uint32_t lrow = (uint32_t)(nL * 64);

    // cp.async per-thread dest offsets (2 chunks of 16B per split)
    const int fn0 = tid >> 2, fc0 = tid & 3;
    const int fn1 = (tid + 256) >> 2, fc1 = (tid + 256) & 3;
    const uint32_t fd0 = (uint32_t)(fn0 * 64 + ((fc0 ^ ((fn0 >> 1) & 3)) << 4));
    const uint32_t fd1 = (uint32_t)(fn1 * 64 + ((fc1 ^ ((fn1 >> 1) & 3)) << 4));

    float acc[16][4];
#pragma unroll
    for (int i = 0; i < 16; i++)
#pragma unroll
        for (int j = 0; j < 4; j++) acc[i][j] = 0.f;

    // ---- fill chunk 0 ----
    {
        const char* sh0 = (const char*)&g_wt_hi[(size_t)fn0 * KPAD + fc0 * 8];
        const char* sh1 = (const char*)&g_wt_hi[(size_t)fn1 * KPAD + fc1 * 8];
        const char* sl0 = (const char*)&g_wt_lo[(size_t)fn0 * KPAD + fc0 * 8];
        const char* sl1 = (const char*)&g_wt_lo[(size_t)fn1 * KPAD + fc1 * 8];
        cp16(sb + fd0, sh0);             cp16(sb + fd1, sh1);
        cp16(sb + 16384 + fd0, sl0);     cp16(sb + 16384 + fd1, sl1);
        asm volatile("cp.async.commit_group;");
        asm volatile("cp.async.wait_group 0;");
    }
    __syncthreads();

    // A raw prefetch for k16 index 0
    const int kc = 2 * c4;   // 0,2,4,6
    float2 araw[4];
    {
        int col = kc;
        araw[0] = *(const float2*)&x[(size_t)r0 * NF + col];
        araw[1] = *(const float2*)&x[(size_t)r1 * NF + col];
        araw[2] = *(const float2*)&x[(size_t)r0 * NF + col + 8];
        araw[3] = *(const float2*)&x[(size_t)r1 * NF + col + 8];
    }

    for (int c = 0; c < NCH; c++) {
        const uint32_t buf = (uint32_t)(c & 1) * 8192u;
        if (c + 1 < NCH) {
            const uint32_t nbuf = (uint32_t)((c + 1) & 1) * 8192u;
            size_t koff = (size_t)(c + 1) * 32;
            const char* sh0 = (const char*)&g_wt_hi[(size_t)fn0 * KPAD + koff + fc0 * 8];
            const char* sh1 = (const char*)&g_wt_hi[(size_t)fn1 * KPAD + koff + fc1 * 8];
            const char* sl0 = (const char*)&g_wt_lo[(size_t)fn0 * KPAD + koff + fc0 * 8];
            const char* sl1 = (const char*)&g_wt_lo[(size_t)fn1 * KPAD + koff + fc1 * 8];
            cp16(sb + nbuf + fd0, sh0);          cp16(sb + nbuf + fd1, sh1);
            cp16(sb + 16384 + nbuf + fd0, sl0);  cp16(sb + 16384 + nbuf + fd1, sl1);
            asm volatile("cp.async.commit_group;");
        }
#pragma unroll
        for (int s = 0; s < 2; s++) {
            // prefetch next k16 A raw (predicated; even ncol bounds both elems)
            float2 anext[4];
            {
                int ncol = (s == 0) ? (c * 32 + 16 + kc) : ((c + 1) * 32 + kc);
                bool p0 = ncol < NF, p1 = (ncol + 8) < NF;
                anext[0] = p0 ? *(const float2*)&x[(size_t)r0 * NF + ncol] : make_float2(0.f, 0.f);
                anext[1] = p0 ? *(const float2*)&x[(size_t)r1 * NF + ncol] : make_float2(0.f, 0.f);
                anext[2] = p1 ? *(const float2*)&x[(size_t)r0 * NF + ncol + 8] : make_float2(0.f, 0.f);
                anext[3] = p1 ? *(const float2*)&x[(size_t)r1 * NF + ncol + 8] : make_float2(0.f, 0.f);
            }
            // convert current A raw -> hi/lo fragments
            uint32_t ah[4], al[4];
#pragma unroll
            for (int i = 0; i < 4; i++) cvt_split(araw[i], ah[i], al[i]);

            const uint32_t loff = lrow + ((uint32_t)(q ^ (s << 1)) << 4);
#pragma unroll
            for (int nb = 0; nb < 8; nb++) {
                uint32_t addr = sb + buf + (uint32_t)(nb * 1024) + loff;
                uint32_t h0, h1, h2, h3, l0, l1, l2, l3;
                ldsm4(h0, h1, h2, h3, addr);
                ldsm4(l0, l1, l2, l3, addr + 16384u);
                float* d0 = acc[nb * 2];
                float* d1 = acc[nb * 2 + 1];
                mma16816(d0, ah[0], ah[1], ah[2], ah[3], h0, h1);
                mma16816(d0, ah[0], ah[1], ah[2], ah[3], l0, l1);
                mma16816(d0, al[0], al[1], al[2], al[3], h0, h1);
                mma16816(d1, ah[0], ah[1], ah[2], ah[3], h2, h3);
                mma16816(d1, ah[0], ah[1], ah[2], ah[3], l2, l3);
                mma16816(d1, al[0], al[1], al[2], al[3], h2, h3);
            }
#pragma unroll
            for (int i = 0; i < 4; i++) araw[i] = anext[i];
        }
        if (c + 1 < NCH) {
            asm volatile("cp.async.wait_group 0;");
            __syncthreads();
        }
    }

    // ---- epilogue: store h1/res ----
    int row0 = mbase + g, row1 = mbase + g + 8;
#pragma unroll
    for (int nf = 0; nf < 16; nf++) {
        int col = nf * 8 + 2 * c4;
        float2 v0 = make_float2(acc[nf][0], acc[nf][1]);
        float2 v1 = make_float2(acc[nf][2], acc[nf][3]);
        if (col < 64) {
            if (row0 < NN) *(float2*)&g_h1[(size_t)row0 * 64 + col] = v0;
            if (row1 < NN) *(float2*)&g_h1[(size_t)row1 * 64 + col] = v1;
        } else {
            int nr = col - 64;
            float b0 = __ldg(&bres[nr]), b1 = __ldg(&bres[nr + 1]);
            v0.x += b0; v0.y += b1; v1.x += b0; v1.y += b1;
            if (row0 < NN) *(float2*)&g_res[(size_t)row0 * 64 + nr] = v0;
            if (row1 < NN) *(float2*)&g_res[(size_t)row1 * 64 + nr] = v1;
        }
    }

    // ---- fused att1: head h = nf (cols nf*8..nf*8+7), quad-reduce over c4 --
#pragma unroll
    for (int nf = 0; nf < 8; nf++) {
        float ws0 = __ldg(&asrc[nf * 8 + 2 * c4]);
        float ws1 = __ldg(&asrc[nf * 8 + 2 * c4 + 1]);
        float wd0 = __ldg(&adst[nf * 8 + 2 * c4]);
        float wd1 = __ldg(&adst[nf * 8 + 2 * c4 + 1]);
        float ps0 = acc[nf][0] * ws0 + acc[nf][1] * ws1;
        float pd0 = acc[nf][0] * wd0 + acc[nf][1] * wd1;
        float ps1 = acc[nf][2] * ws0 + acc[nf][3] * ws1;
        float pd1 = acc[nf][2] * wd0 + acc[nf][3] * wd1;
        ps0 += __shfl_xor_sync(0xffffffffu, ps0, 1);
        ps0 += __shfl_xor_sync(0xffffffffu, ps0, 2);
        pd0 += __shfl_xor_sync(0xffffffffu, pd0, 1);
        pd0 += __shfl_xor_sync(0xffffffffu, pd0, 2);
        ps1 += __shfl_xor_sync(0xffffffffu, ps1, 1);
        ps1 += __shfl_xor_sync(0xffffffffu, ps1, 2);
        pd1 += __shfl_xor_sync(0xffffffffu, pd1, 1);
        pd1 += __shfl_xor_sync(0xffffffffu, pd1, 2);
        if (c4 == 0) {
            if (row0 < NN) { g_as1[row0 * 8 + nf] = ps0; g_ad1[row0 * 8 + nf] = pd0; }
            if (row1 < NN) { g_as1[row1 * 8 + nf] = ps1; g_ad1[row1 * 8 + nf] = pd1; }
        }
    }
}

// ---------------- edge pass 1a: exp-sum (recompute model) ------------------
__global__ void k_esum1(const int* __restrict__ ei, int E, int Etot) {
    int e = blockIdx.x * blockDim.x + threadIdx.x;
    if (e >= Etot) return;
    int s, d; edge_sd(ei, E, e, s, d);
    float4 s0 = *(const float4*)&g_as1[s * 8];
    float4 s1 = *(const float4*)&g_as1[s * 8 + 4];
    float4 d0 = *(const float4*)&g_ad1[d * 8];
    float4 d1 = *(const float4*)&g_ad1[d * 8 + 4];
    float v[8] = {s0.x + d0.x, s0.y + d0.y, s0.z + d0.z, s0.w + d0.w,
                  s1.x + d1.x, s1.y + d1.y, s1.z + d1.z, s1.w + d1.w};
    float ev[8];
#pragma unroll
    for (int h = 0; h < 8; h++) {
        float t = (v[h] > 0.f) ? v[h] : 0.2f * v[h];
        ev[h] = __expf(t);
    }
    red_add_v4(&g_sum1[d * 8],     ev[0], ev[1], ev[2], ev[3]);
    red_add_v4(&g_sum1[d * 8 + 4], ev[4], ev[5], ev[6], ev[7]);
}

// ---------------- edge pass 1b: alpha + message scatter --------------------
__global__ void k_emsg1(const int* __restrict__ ei, int E, int Etot,
                        float* __restrict__ a1out) {
    int e = blockIdx.x * blockDim.x + threadIdx.x;
    if (e >= Etot) return;
    int s, d; edge_sd(ei, E, e, s, d);
    float4 s0 = *(const float4*)&g_as1[s * 8];
    float4 s1 = *(const float4*)&g_as1[s * 8 + 4];
    float4 d0 = *(const float4*)&g_ad1[d * 8];
    float4 d1 = *(const float4*)&g_ad1[d * 8 + 4];
    float v[8] = {s0.x + d0.x, s0.y + d0.y, s0.z + d0.z, s0.w + d0.w,
                  s1.x + d1.x, s1.y + d1.y, s1.z + d1.z, s1.w + d1.w};
    float4 q0 = *(const float4*)&g_sum1[d * 8];
    float4 q1 = *(const float4*)&g_sum1[d * 8 + 4];
    float qs[8] = {q0.x, q0.y, q0.z, q0.w, q1.x, q1.y, q1.z, q1.w};
    float alpha[8];
#pragma unroll
    for (int h = 0; h < 8; h++) {
        float t = (v[h] > 0.f) ? v[h] : 0.2f * v[h];
        alpha[h] = __expf(t) / (qs[h] + 1e-16f);
    }
    if (a1out) {
        *(float4*)&a1out[(size_t)e * 8]     = make_float4(alpha[0], alpha[1], alpha[2], alpha[3]);
        *(float4*)&a1out[(size_t)e * 8 + 4] = make_float4(alpha[4], alpha[5], alpha[6], alpha[7]);
    }
    const float* hr = &g_h1[(size_t)s * 64];
    float* o = &g_out1[(size_t)d * 64];
#pragma unroll
    for (int h = 0; h < 8; h++) {
        float a = alpha[h];
        float4 h0 = *(const float4*)&hr[h * 8];
        float4 h1v = *(const float4*)&hr[h * 8 + 4];
        red_add_v4(o + h * 8,     h0.x * a, h0.y * a, h0.z * a, h0.w * a);
        red_add_v4(o + h * 8 + 4, h1v.x * a, h1v.y * a, h1v.z * a, h1v.w * a);
    }
}

// ---------------- GEMM2 (+ fused x1 elu) + att2 coefficients ---------------
__global__ __launch_bounds__(128) void k_gemm2(const float* __restrict__ w2,
                                               const float* __restrict__ watt_s,
                                               const float* __restrict__ watt_d,
                                               const float* __restrict__ b1) {
    __shared__ float sw[64 * NC];
    __shared__ float ss[NC], sd[NC];
    __shared__ float sb1[64];
    int tid = threadIdx.x;
    for (int i = tid; i < 64 * NC; i += blockDim.x) sw[i] = w2[i];
    if (tid < NC) { ss[tid] = watt_s[tid]; sd[tid] = watt_d[tid]; }
    if (tid < 64) sb1[tid] = b1[tid];
    __syncthreads();
    int n = blockIdx.x * blockDim.x + tid;
    if (n >= NN) return;
    float r[64];
    const float4* orow = (const float4*)&g_out1[(size_t)n * 64];
    const float4* rrow = (const float4*)&g_res[(size_t)n * 64];
#pragma unroll
    for (int i = 0; i < 16; i++) {
        float4 o = orow[i];
        float4 rr = rrow[i];
        float t0 = o.x + sb1[i * 4 + 0] + rr.x;
        float t1 = o.y + sb1[i * 4 + 1] + rr.y;
        float t2 = o.z + sb1[i * 4 + 2] + rr.z;
        float t3 = o.w + sb1[i * 4 + 3] + rr.w;
        r[i * 4 + 0] = (t0 > 0.f) ? t0 : expm1f(t0);
        r[i * 4 + 1] = (t1 > 0.f) ? t1 : expm1f(t1);
        r[i * 4 + 2] = (t2 > 0.f) ? t2 : expm1f(t2);
        r[i * 4 + 3] = (t3 > 0.f) ? t3 : expm1f(t3);
    }
    float as = 0.f, ad = 0.f;
#pragma unroll
    for (int j = 0; j < NC; j++) {
        float sacc = 0.f;
#pragma unroll
        for (int k = 0; k < 64; k++) sacc += r[k] * sw[k * NC + j];
        g_h2[(size_t)n * NCP + j] = sacc;
        as += sacc * ss[j];
        ad += sacc * sd[j];
    }
    g_as2[n] = as;
    g_ad2[n] = ad;
}

// ---------------- edge passes layer 2 (H=1, C=30; recompute model) ---------
__global__ void k_esum2(const int* __restrict__ ei, int E, int Etot) {
    int e = blockIdx.x * blockDim.x + threadIdx.x;
    if (e >= Etot) return;
    int s, d; edge_sd(ei, E, e, s, d);
    float v = g_as2[s] + g_ad2[d];
    v = (v > 0.f) ? v : 0.2f * v;
    atomicAdd(&g_sum2[d], __expf(v));
}

__global__ void k_emsg2(const int* __restrict__ ei, int E, int Etot,
                        float* __restrict__ a2out) {
    int e = blockIdx.x * blockDim.x + threadIdx.x;
    if (e >= Etot) return;
    int s, d; edge_sd(ei, E, e, s, d);
    float v = g_as2[s] + g_ad2[d];
    v = (v > 0.f) ? v : 0.2f * v;
    float alpha = __expf(v) / (g_sum2[d] + 1e-16f);
    if (a2out) a2out[e] = alpha;
    const float4* hp = (const float4*)&g_h2[(size_t)s * NCP];
    float* op = &g_out2[(size_t)d * NCP];
#pragma unroll
    for (int q = 0; q < 7; q++) {
        float4 vv = hp[q];
        red_add_v4(op + q * 4, vv.x * alpha, vv.y * alpha, vv.z * alpha, vv.w * alpha);
    }
    float2 t = *(const float2*)&g_h2[(size_t)s * NCP + 28];
    red_add_v2(op + 28, t.x * alpha, t.y * alpha);
}

// ---------------- final: elu(out2 + b2), log_softmax ----------------
__global__ void k_final(const float* __restrict__ b2, float* __restrict__ out) {
    int n = blockIdx.x * blockDim.x + threadIdx.x;
    if (n >= NN) return;
    float v[NC];
    float m = -INFINITY;
#pragma unroll
    for (int c = 0; c < NC; c++) {
        float t = g_out2[(size_t)n * NCP + c] + __ldg(&b2[c]);
        t = (t > 0.f) ? t : expm1f(t);
        v[c] = t;
        m = fmaxf(m, t);
    }
    float ssum = 0.f;
#pragma unroll
    for (int c = 0; c < NC; c++) ssum += expf(v[c] - m);
    float lse = m + logf(ssum);
#pragma unroll
    for (int c = 0; c < NC; c++) out[(size_t)n * NC + c] = v[c] - lse;
}

// ---------------- launch ----------------
extern "C" void kernel_launch(void* const* d_in, const int* in_sizes, int n_in,
                              void* d_out, int out_size) {
    const float* x      = (const float*)d_in[0];
    const int*   ei     = (const int*)d_in[1];
    const float* w_res  = (const float*)d_in[2];
    const float* b_res  = (const float*)d_in[3];
    const float* w1     = (const float*)d_in[4];
    const float* att_s1 = (const float*)d_in[5];
    const float* att_d1 = (const float*)d_in[6];
    const float* b1     = (const float*)d_in[7];
    const float* w2     = (const float*)d_in[8];
    const float* att_s2 = (const float*)d_in[9];
    const float* att_d2 = (const float*)d_in[10];
    const float* b2     = (const float*)d_in[11];

    int E = in_sizes[1] / 2;
    int Etot = E + NN;

    float* out = (float*)d_out;
    long long need = (long long)NN * NC + (long long)Etot * HEADS + (long long)Etot;
    float *a1out = nullptr, *a2out = nullptr;
    if ((long long)out_size >= need) {
        a1out = out + (size_t)NN * NC;
        a2out = a1out + (size_t)Etot * HEADS;
    }

    k_init_all<<<(NN * D1 + 255) / 256, 256>>>();
    k_prep_w<<<(128 * KPAD + 255) / 256, 256>>>(w1, w_res);
    k_gemm1<<<(NN + 127) / 128, 256>>>(x, b_res, att_s1, att_d1);

    k_esum1<<<(Etot + 255) / 256, 256>>>(ei, E, Etot);
    k_emsg1<<<(Etot + 255) / 256, 256>>>(ei, E, Etot, a1out);

    k_gemm2<<<(NN + 127) / 128, 128>>>(w2, att_s2, att_d2, b1);

    k_esum2<<<(Etot + 255) / 256, 256>>>(ei, E, Etot);
    k_emsg2<<<(Etot + 255) / 256, 256>>>(ei, E, Etot, a2out);

    k_final<<<(NN + 127) / 128, 128>>>(b2, out);
}

// round 12
// speedup vs baseline: 1.0196x; 1.0196x over previous
#include <cuda_runtime.h>
#include <cuda_bf16.h>
#include <math.h>
#include <stdint.h>

// Problem constants (fixed shapes per reference)
#define NN    50000
#define NF    2000
#define KPAD  2048
#define D1    64
#define HEADS 8
#define HID   8
#define NC    30
#define NCP   32
#define MAXET 1700000

// ---------------- scratch (device globals; no allocation allowed) ----------
__device__ float g_h1[(size_t)NN * D1];
__device__ float g_res[(size_t)NN * D1];
__device__ float g_as1[NN * HEADS];
__device__ float g_ad1[NN * HEADS];
__device__ float g_sum1[NN * HEADS];
__device__ float g_eb1[(size_t)MAXET * HEADS];
__device__ float g_out1[(size_t)NN * D1];
__device__ float g_h2[(size_t)NN * NCP];
__device__ float g_as2[NN];
__device__ float g_ad2[NN];
__device__ float g_sum2[NN];
__device__ float g_eb2[MAXET];
__device__ float g_out2[(size_t)NN * NCP];
// pre-transposed + split weights: [n=0..127][k=0..2047] bf16 (zeros past NF)
__device__ unsigned short g_wt_hi[128 * KPAD];
__device__ unsigned short g_wt_lo[128 * KPAD];

// ---------------- helpers ----------------
__device__ __forceinline__ void edge_sd(const int* __restrict__ ei, int E, int e,
                                        int& s, int& d) {
    if (e < E) { s = ei[e]; d = ei[E + e]; }
    else       { s = e - E; d = e - E; }
}
__device__ __forceinline__ void red_add_v4(float* addr, float a, float b, float c, float d) {
    asm volatile("red.global.add.v4.f32 [%0], {%1,%2,%3,%4};"
                 :: "l"(addr), "f"(a), "f"(b), "f"(c), "f"(d) : "memory");
}
__device__ __forceinline__ void red_add_v2(float* addr, float a, float b) {
    asm volatile("red.global.add.v2.f32 [%0], {%1,%2};"
                 :: "l"(addr), "f"(a), "f"(b) : "memory");
}
__device__ __forceinline__ uint32_t smem_u32(const void* p) {
    uint32_t a;
    asm("{ .reg .u64 t; cvta.to.shared.u64 t, %1; cvt.u32.u64 %0, t; }" : "=r"(a) : "l"(p));
    return a;
}
// pack two floats -> bf16x2: first arg to UPPER half, second to LOWER half
__device__ __forceinline__ uint32_t pack_bf16x2(float h, float l) {
    uint32_t r;
    asm("cvt.rn.bf16x2.f32 %0, %1, %2;" : "=r"(r) : "f"(h), "f"(l));
    return r;
}
__device__ __forceinline__ void ldsm4(uint32_t& r0, uint32_t& r1, uint32_t& r2,
                                      uint32_t& r3, uint32_t addr) {
    asm volatile("ldmatrix.sync.aligned.m8n8.x4.shared.b16 {%0,%1,%2,%3}, [%4];"
                 : "=r"(r0), "=r"(r1), "=r"(r2), "=r"(r3) : "r"(addr));
}
__device__ __forceinline__ void mma16816(float* d, uint32_t a0, uint32_t a1,
                                         uint32_t a2, uint32_t a3,
                                         uint32_t b0, uint32_t b1) {
    asm volatile("mma.sync.aligned.m16n8k16.row.col.f32.bf16.bf16.f32 "
                 "{%0,%1,%2,%3}, {%4,%5,%6,%7}, {%8,%9}, {%0,%1,%2,%3};"
                 : "+f"(d[0]), "+f"(d[1]), "+f"(d[2]), "+f"(d[3])
                 : "r"(a0), "r"(a1), "r"(a2), "r"(a3), "r"(b0), "r"(b1));
}
__device__ __forceinline__ void cp16(uint32_t smaddr, const void* gptr) {
    asm volatile("cp.async.cg.shared.global [%0], [%1], 16;"
                 :: "r"(smaddr), "l"(gptr) : "memory");
}
// split fp32 pair -> bf16x2 (hi = truncation, lo = RN residual)
__device__ __forceinline__ void cvt_split(float2 v, uint32_t& hi, uint32_t& lo) {
    uint32_t vx = __float_as_uint(v.x), vy = __float_as_uint(v.y);
    hi = __byte_perm(vx, vy, 0x7632);      // low half = bf16_trunc(v.x), high = v.y
    float hx = __uint_as_float(vx & 0xFFFF0000u);
    float hy = __uint_as_float(vy & 0xFFFF0000u);
    lo = pack_bf16x2(v.y - hy, v.x - hx);
}

// ---------------- init (float4 stores) ----------------
__global__ void k_init_all() {
    int i = blockIdx.x * blockDim.x + threadIdx.x;   // float4 index
    float4 z = make_float4(0.f, 0.f, 0.f, 0.f);
    if (i < NN * D1 / 4)    ((float4*)g_out1)[i] = z;
    if (i < NN * NCP / 4)   ((float4*)g_out2)[i] = z;
    if (i < NN * HEADS / 4) ((float4*)g_sum1)[i] = z;
    if (i < NN / 4)         ((float4*)g_sum2)[i] = z;
}

// ---------------- prep: transpose + bf16-split weights -------------------
__global__ void k_prep_w(const float* __restrict__ w1, const float* __restrict__ wres) {
    int idx = blockIdx.x * blockDim.x + threadIdx.x;
    if (idx >= 128 * KPAD) return;
    int n = idx >> 11;
    int k = idx & (KPAD - 1);
    float v = 0.f;
    if (k < NF) v = (n < 64) ? w1[(size_t)k * 64 + n] : wres[(size_t)k * 64 + (n - 64)];
    __nv_bfloat16 hi = __float2bfloat16(v);
    float rem = v - __bfloat162float(hi);
    __nv_bfloat16 lo = __float2bfloat16(rem);
    g_wt_hi[idx] = __bfloat16_as_ushort(hi);
    g_wt_lo[idx] = __bfloat16_as_ushort(lo);
}

// ---------------- GEMM1 via mma.sync bf16x3 + fused att1 ------------------
// [h1 | res] = x @ [w1 | wres]; as1/ad1 computed in-epilogue via quad shfl.
// 256 threads = 8 warps; warp w owns rows mbase+w*16. BK=32, 63 chunks.
// D = Ahi*Bhi + Ahi*Blo + Alo*Bhi  (bf16x3; rel err ~1e-5)
#define NCH 63

__global__ __launch_bounds__(256, 2) void k_gemm1(const float* __restrict__ x,
                                                  const float* __restrict__ bres,
                                                  const float* __restrict__ asrc,
                                                  const float* __restrict__ adst) {
    __shared__ __align__(1024) unsigned char Bsm[32768]; // HI:0/8192, LO:16384/24576

    const int tid = threadIdx.x, wid = tid >> 5, lane = tid & 31;
    const int g = lane >> 2, c4 = lane & 3;
    const int mbase = blockIdx.x * 128 + wid * 16;
    int r0 = mbase + g;      if (r0 >= NN) r0 = NN - 1;
    int r1 = mbase + g + 8;  if (r1 >= NN) r1 = NN - 1;
    const uint32_t sb = smem_u32(Bsm);

    // ldmatrix per-lane constants
    const int nL   = (lane & 7) | ((lane & 16) >> 1);  // 0..15
    const int cbit = (lane >> 3) & 1;
    const int q    = cbit ^ ((nL >> 1) & 3);
    const uint32_t lrow = (uint32_t)(nL * 64);

    // cp.async per-thread dest offsets (2 chunks of 16B per split)
    const int fn0 = tid >> 2, fc0 = tid & 3;
    const int fn1 = (tid + 256) >> 2, fc1 = (tid + 256) & 3;
    const uint32_t fd0 = (uint32_t)(fn0 * 64 + ((fc0 ^ ((fn0 >> 1) & 3)) << 4));
    const uint32_t fd1 = (uint32_t)(fn1 * 64 + ((fc1 ^ ((fn1 >> 1) & 3)) << 4));

    float acc[16][4];
#pragma unroll
    for (int i = 0; i < 16; i++)
#pragma unroll
        for (int j = 0; j < 4; j++) acc[i][j] = 0.f;

    // ---- fill chunk 0 ----
    {
        const char* sh0 = (const char*)&g_wt_hi[(size_t)fn0 * KPAD + fc0 * 8];
        const char* sh1 = (const char*)&g_wt_hi[(size_t)fn1 * KPAD + fc1 * 8];
        const char* sl0 = (const char*)&g_wt_lo[(size_t)fn0 * KPAD + fc0 * 8];
        const char* sl1 = (const char*)&g_wt_lo[(size_t)fn1 * KPAD + fc1 * 8];
        cp16(sb + fd0, sh0);             cp16(sb + fd1, sh1);
        cp16(sb + 16384 + fd0, sl0);     cp16(sb + 16384 + fd1, sl1);
        asm volatile("cp.async.commit_group;");
        asm volatile("cp.async.wait_group 0;");
    }
    __syncthreads();

    // A raw prefetch for k16 index 0
    const int kc = 2 * c4;   // 0,2,4,6
    float2 araw[4];
    {
        int col = kc;
        araw[0] = *(const float2*)&x[(size_t)r0 * NF + col];
        araw[1] = *(const float2*)&x[(size_t)r1 * NF + col];
        araw[2] = *(const float2*)&x[(size_t)r0 * NF + col + 8];
        araw[3] = *(const float2*)&x[(size_t)r1 * NF + col + 8];
    }

    for (int c = 0; c < NCH; c++) {
        const uint32_t buf = (uint32_t)(c & 1) * 8192u;
        if (c + 1 < NCH) {
            const uint32_t nbuf = (uint32_t)((c + 1) & 1) * 8192u;
            size_t koff = (size_t)(c + 1) * 32;
            const char* sh0 = (const char*)&g_wt_hi[(size_t)fn0 * KPAD + koff + fc0 * 8];
            const char* sh1 = (const char*)&g_wt_hi[(size_t)fn1 * KPAD + koff + fc1 * 8];
            const char* sl0 = (const char*)&g_wt_lo[(size_t)fn0 * KPAD + koff + fc0 * 8];
            const char* sl1 = (const char*)&g_wt_lo[(size_t)fn1 * KPAD + koff + fc1 * 8];
            cp16(sb + nbuf + fd0, sh0);          cp16(sb + nbuf + fd1, sh1);
            cp16(sb + 16384 + nbuf + fd0, sl0);  cp16(sb + 16384 + nbuf + fd1, sl1);
            asm volatile("cp.async.commit_group;");
        }
#pragma unroll
        for (int s = 0; s < 2; s++) {
            // prefetch next k16 A raw (predicated; even ncol bounds both elems)
            float2 anext[4];
            {
                int ncol = (s == 0) ? (c * 32 + 16 + kc) : ((c + 1) * 32 + kc);
                bool p0 = ncol < NF, p1 = (ncol + 8) < NF;
                anext[0] = p0 ? *(const float2*)&x[(size_t)r0 * NF + ncol] : make_float2(0.f, 0.f);
                anext[1] = p0 ? *(const float2*)&x[(size_t)r1 * NF + ncol] : make_float2(0.f, 0.f);
                anext[2] = p1 ? *(const float2*)&x[(size_t)r0 * NF + ncol + 8] : make_float2(0.f, 0.f);
                anext[3] = p1 ? *(const float2*)&x[(size_t)r1 * NF + ncol + 8] : make_float2(0.f, 0.f);
            }
            // convert current A raw -> hi/lo fragments
            uint32_t ah[4], al[4];
#pragma unroll
            for (int i = 0; i < 4; i++) cvt_split(araw[i], ah[i], al[i]);

            const uint32_t loff = lrow + ((uint32_t)(q ^ (s << 1)) << 4);
#pragma unroll
            for (int nb = 0; nb < 8; nb++) {
                uint32_t addr = sb + buf + (uint32_t)(nb * 1024) + loff;
                uint32_t h0, h1, h2, h3, l0, l1, l2, l3;
                ldsm4(h0, h1, h2, h3, addr);
                ldsm4(l0, l1, l2, l3, addr + 16384u);
                float* d0 = acc[nb * 2];
                float* d1 = acc[nb * 2 + 1];
                mma16816(d0, ah[0], ah[1], ah[2], ah[3], h0, h1);
                mma16816(d0, ah[0], ah[1], ah[2], ah[3], l0, l1);
                mma16816(d0, al[0], al[1], al[2], al[3], h0, h1);
                mma16816(d1, ah[0], ah[1], ah[2], ah[3], h2, h3);
                mma16816(d1, ah[0], ah[1], ah[2], ah[3], l2, l3);
                mma16816(d1, al[0], al[1], al[2], al[3], h2, h3);
            }
#pragma unroll
            for (int i = 0; i < 4; i++) araw[i] = anext[i];
        }
        if (c + 1 < NCH) {
            asm volatile("cp.async.wait_group 0;");
            __syncthreads();
        }
    }

    // ---- epilogue: store h1/res ----
    int row0 = mbase + g, row1 = mbase + g + 8;
#pragma unroll
    for (int nf = 0; nf < 16; nf++) {
        int col = nf * 8 + 2 * c4;
        float2 v0 = make_float2(acc[nf][0], acc[nf][1]);
        float2 v1 = make_float2(acc[nf][2], acc[nf][3]);
        if (col < 64) {
            if (row0 < NN) *(float2*)&g_h1[(size_t)row0 * 64 + col] = v0;
            if (row1 < NN) *(float2*)&g_h1[(size_t)row1 * 64 + col] = v1;
        } else {
            int nr = col - 64;
            float b0 = __ldg(&bres[nr]), b1 = __ldg(&bres[nr + 1]);
            v0.x += b0; v0.y += b1; v1.x += b0; v1.y += b1;
            if (row0 < NN) *(float2*)&g_res[(size_t)row0 * 64 + nr] = v0;
            if (row1 < NN) *(float2*)&g_res[(size_t)row1 * 64 + nr] = v1;
        }
    }

    // ---- fused att1: head h = nf (cols nf*8..nf*8+7), quad-reduce over c4 --
#pragma unroll
    for (int nf = 0; nf < 8; nf++) {
        float ws0 = __ldg(&asrc[nf * 8 + 2 * c4]);
        float ws1 = __ldg(&asrc[nf * 8 + 2 * c4 + 1]);
        float wd0 = __ldg(&adst[nf * 8 + 2 * c4]);
        float wd1 = __ldg(&adst[nf * 8 + 2 * c4 + 1]);
        float ps0 = acc[nf][0] * ws0 + acc[nf][1] * ws1;
        float pd0 = acc[nf][0] * wd0 + acc[nf][1] * wd1;
        float ps1 = acc[nf][2] * ws0 + acc[nf][3] * ws1;
        float pd1 = acc[nf][2] * wd0 + acc[nf][3] * wd1;
        ps0 += __shfl_xor_sync(0xffffffffu, ps0, 1);
        ps0 += __shfl_xor_sync(0xffffffffu, ps0, 2);
        pd0 += __shfl_xor_sync(0xffffffffu, pd0, 1);
        pd0 += __shfl_xor_sync(0xffffffffu, pd0, 2);
        ps1 += __shfl_xor_sync(0xffffffffu, ps1, 1);
        ps1 += __shfl_xor_sync(0xffffffffu, ps1, 2);
        pd1 += __shfl_xor_sync(0xffffffffu, pd1, 1);
        pd1 += __shfl_xor_sync(0xffffffffu, pd1, 2);
        if (c4 == 0) {
            if (row0 < NN) { g_as1[row0 * 8 + nf] = ps0; g_ad1[row0 * 8 + nf] = pd0; }
            if (row1 < NN) { g_as1[row1 * 8 + nf] = ps1; g_ad1[row1 * 8 + nf] = pd1; }
        }
    }
}

// ---------------- edge pass 1a: exp + store + sum (R10 model) --------------
__global__ void k_esum1(const int* __restrict__ ei, int E, int Etot) {
    int e = blockIdx.x * blockDim.x + threadIdx.x;
    if (e >= Etot) return;
    int s, d; edge_sd(ei, E, e, s, d);
    float4 s0 = *(const float4*)&g_as1[s * 8];
    float4 s1 = *(const float4*)&g_as1[s * 8 + 4];
    float4 d0 = *(const float4*)&g_ad1[d * 8];
    float4 d1 = *(const float4*)&g_ad1[d * 8 + 4];
    float v[8] = {s0.x + d0.x, s0.y + d0.y, s0.z + d0.z, s0.w + d0.w,
                  s1.x + d1.x, s1.y + d1.y, s1.z + d1.z, s1.w + d1.w};
    float ev[8];
#pragma unroll
    for (int h = 0; h < 8; h++) {
        float t = (v[h] > 0.f) ? v[h] : 0.2f * v[h];
        ev[h] = __expf(t);
    }
    *(float4*)&g_eb1[(size_t)e * 8]     = make_float4(ev[0], ev[1], ev[2], ev[3]);
    *(float4*)&g_eb1[(size_t)e * 8 + 4] = make_float4(ev[4], ev[5], ev[6], ev[7]);
    red_add_v4(&g_sum1[d * 8],     ev[0], ev[1], ev[2], ev[3]);
    red_add_v4(&g_sum1[d * 8 + 4], ev[4], ev[5], ev[6], ev[7]);
}

// ---------------- edge pass 1b: alpha + message scatter --------------------
__global__ void k_emsg1(const int* __restrict__ ei, int E, int Etot,
                        float* __restrict__ a1out) {
    int e = blockIdx.x * blockDim.x + threadIdx.x;
    if (e >= Etot) return;
    int s, d; edge_sd(ei, E, e, s, d);
    float4 e0 = *(const float4*)&g_eb1[(size_t)e * 8];
    float4 e1 = *(const float4*)&g_eb1[(size_t)e * 8 + 4];
    float4 q0 = *(const float4*)&g_sum1[d * 8];
    float4 q1 = *(const float4*)&g_sum1[d * 8 + 4];
    float alpha[8] = {e0.x / (q0.x + 1e-16f), e0.y / (q0.y + 1e-16f),
                      e0.z / (q0.z + 1e-16f), e0.w / (q0.w + 1e-16f),
                      e1.x / (q1.x + 1e-16f), e1.y / (q1.y + 1e-16f),
                      e1.z / (q1.z + 1e-16f), e1.w / (q1.w + 1e-16f)};
    if (a1out) {
        *(float4*)&a1out[(size_t)e * 8]     = make_float4(alpha[0], alpha[1], alpha[2], alpha[3]);
        *(float4*)&a1out[(size_t)e * 8 + 4] = make_float4(alpha[4], alpha[5], alpha[6], alpha[7]);
    }
    const float* hr = &g_h1[(size_t)s * 64];
    float* o = &g_out1[(size_t)d * 64];
#pragma unroll
    for (int h = 0; h < 8; h++) {
        float a = alpha[h];
        float4 h0 = *(const float4*)&hr[h * 8];
        float4 h1v = *(const float4*)&hr[h * 8 + 4];
        red_add_v4(o + h * 8,     h0.x * a, h0.y * a, h0.z * a, h0.w * a);
        red_add_v4(o + h * 8 + 4, h1v.x * a, h1v.y * a, h1v.z * a, h1v.w * a);
    }
}

// ---------------- GEMM2 (+ fused x1 elu) + att2 coefficients ---------------
__global__ __launch_bounds__(128) void k_gemm2(const float* __restrict__ w2,
                                               const float* __restrict__ watt_s,
                                               const float* __restrict__ watt_d,
                                               const float* __restrict__ b1) {
    __shared__ float sw[64 * NC];
    __shared__ float ss[NC], sd[NC];
    __shared__ float sb1[64];
    int tid = threadIdx.x;
    for (int i = tid; i < 64 * NC; i += blockDim.x) sw[i] = w2[i];
    if (tid < NC) { ss[tid] = watt_s[tid]; sd[tid] = watt_d[tid]; }
    if (tid < 64) sb1[tid] = b1[tid];
    __syncthreads();
    int n = blockIdx.x * blockDim.x + tid;
    if (n >= NN) return;
    float r[64];
    const float4* orow = (const float4*)&g_out1[(size_t)n * 64];
    const float4* rrow = (const float4*)&g_res[(size_t)n * 64];
#pragma unroll
    for (int i = 0; i < 16; i++) {
        float4 o = orow[i];
        float4 rr = rrow[i];
        float t0 = o.x + sb1[i * 4 + 0] + rr.x;
        float t1 = o.y + sb1[i * 4 + 1] + rr.y;
        float t2 = o.z + sb1[i * 4 + 2] + rr.z;
        float t3 = o.w + sb1[i * 4 + 3] + rr.w;
        r[i * 4 + 0] = (t0 > 0.f) ? t0 : expm1f(t0);
        r[i * 4 + 1] = (t1 > 0.f) ? t1 : expm1f(t1);
        r[i * 4 + 2] = (t2 > 0.f) ? t2 : expm1f(t2);
        r[i * 4 + 3] = (t3 > 0.f) ? t3 : expm1f(t3);
    }
    float as = 0.f, ad = 0.f;
#pragma unroll
    for (int j = 0; j < NC; j++) {
        float sacc = 0.f;
#pragma unroll
        for (int k = 0; k < 64; k++) sacc += r[k] * sw[k * NC + j];
        g_h2[(size_t)n * NCP + j] = sacc;
        as += sacc * ss[j];
        ad += sacc * sd[j];
    }
    g_as2[n] = as;
    g_ad2[n] = ad;
}

// ---------------- edge passes layer 2 (H=1, C=30; store model) -------------
__global__ void k_esum2(const int* __restrict__ ei, int E, int Etot) {
    int e = blockIdx.x * blockDim.x + threadIdx.x;
    if (e >= Etot) return;
    int s, d; edge_sd(ei, E, e, s, d);
    float v = g_as2[s] + g_ad2[d];
    v = (v > 0.f) ? v : 0.2f * v;
    float ev = __expf(v);
    g_eb2[e] = ev;
    atomicAdd(&g_sum2[d], ev);
}

__global__ void k_emsg2(const int* __restrict__ ei, int E, int Etot,
                        float* __restrict__ a2out) {
    int e = blockIdx.x * blockDim.x + threadIdx.x;
    if (e >= Etot) return;
    int s, d; edge_sd(ei, E, e, s, d);
    float alpha = g_eb2[e] / (g_sum2[d] + 1e-16f);
    if (a2out) a2out[e] = alpha;
    const float4* hp = (const float4*)&g_h2[(size_t)s * NCP];
    float* op = &g_out2[(size_t)d * NCP];
#pragma unroll
    for (int q = 0; q < 7; q++) {
        float4 vv = hp[q];
        red_add_v4(op + q * 4, vv.x * alpha, vv.y * alpha, vv.z * alpha, vv.w * alpha);
    }
    float2 t = *(const float2*)&g_h2[(size_t)s * NCP + 28];
    red_add_v2(op + 28, t.x * alpha, t.y * alpha);
}

// ---------------- final: elu(out2 + b2), log_softmax ----------------
__global__ void k_final(const float* __restrict__ b2, float* __restrict__ out) {
    int n = blockIdx.x * blockDim.x + threadIdx.x;
    if (n >= NN) return;
    float v[NC];
    float m = -INFINITY;
#pragma unroll
    for (int c = 0; c < NC; c++) {
        float t = g_out2[(size_t)n * NCP + c] + __ldg(&b2[c]);
        t = (t > 0.f) ? t : expm1f(t);
        v[c] = t;
        m = fmaxf(m, t);
    }
    float ssum = 0.f;
#pragma unroll
    for (int c = 0; c < NC; c++) ssum += expf(v[c] - m);
    float lse = m + logf(ssum);
#pragma unroll
    for (int c = 0; c < NC; c++) out[(size_t)n * NC + c] = v[c] - lse;
}

// ---------------- launch ----------------
extern "C" void kernel_launch(void* const* d_in, const int* in_sizes, int n_in,
                              void* d_out, int out_size) {
    const float* x      = (const float*)d_in[0];
    const int*   ei     = (const int*)d_in[1];
    const float* w_res  = (const float*)d_in[2];
    const float* b_res  = (const float*)d_in[3];
    const float* w1     = (const float*)d_in[4];
    const float* att_s1 = (const float*)d_in[5];
    const float* att_d1 = (const float*)d_in[6];
    const float* b1     = (const float*)d_in[7];
    const float* w2     = (const float*)d_in[8];
    const float* att_s2 = (const float*)d_in[9];
    const float* att_d2 = (const float*)d_in[10];
    const float* b2     = (const float*)d_in[11];

    int E = in_sizes[1] / 2;
    int Etot = E + NN;

    float* out = (float*)d_out;
    long long need = (long long)NN * NC + (long long)Etot * HEADS + (long long)Etot;
    float *a1out = nullptr, *a2out = nullptr;
    if ((long long)out_size >= need) {
        a1out = out + (size_t)NN * NC;
        a2out = a1out + (size_t)Etot * HEADS;
    }

    k_init_all<<<(NN * D1 / 4 + 255) / 256, 256>>>();
    k_prep_w<<<(128 * KPAD + 255) / 256, 256>>>(w1, w_res);
    k_gemm1<<<(NN + 127) / 128, 256>>>(x, b_res, att_s1, att_d1);

    k_esum1<<<(Etot + 255) / 256, 256>>>(ei, E, Etot);
    k_emsg1<<<(Etot + 255) / 256, 256>>>(ei, E, Etot, a1out);

    k_gemm2<<<(NN + 127) / 128, 128>>>(w2, att_s2, att_d2, b1);

    k_esum2<<<(Etot + 255) / 256, 256>>>(ei, E, Etot);
    k_emsg2<<<(Etot + 255) / 256, 256>>>(ei, E, Etot, a2out);

    k_final<<<(NN + 127) / 128, 128>>>(b2, out);
}

// round 13
// speedup vs baseline: 1.1353x; 1.1135x over previous
#include <cuda_runtime.h>
#include <cuda_bf16.h>
#include <math.h>
#include <stdint.h>

// Problem constants (fixed shapes per reference)
#define NN    50000
#define NF    2000
#define KPAD  2048
#define D1    64
#define HEADS 8
#define HID   8
#define NC    30
#define NCP   32
#define MAXET 1700000

// ---------------- scratch (device globals; no allocation allowed) ----------
__device__ float g_h1[(size_t)NN * D1];
__device__ float g_res[(size_t)NN * D1];
__device__ float g_as1[NN * HEADS];
__device__ float g_ad1[NN * HEADS];
__device__ float g_sum1[NN * HEADS];
__device__ float g_eb1[(size_t)MAXET * HEADS];
__device__ float g_out1[(size_t)NN * D1];
__device__ float g_h2[(size_t)NN * NCP];
__device__ float g_as2[NN];
__device__ float g_ad2[NN];
__device__ float g_sum2[NN];
__device__ float g_eb2[MAXET];
__device__ float g_out2[(size_t)NN * NCP];
// pre-transposed + split weights: [n=0..127][k=0..2047] bf16 (zeros past NF)
__device__ unsigned short g_wt_hi[128 * KPAD];
__device__ unsigned short g_wt_lo[128 * KPAD];

// ---------------- helpers ----------------
__device__ __forceinline__ void edge_sd(const int* __restrict__ ei, int E, int e,
                                        int& s, int& d) {
    if (e < E) { s = ei[e]; d = ei[E + e]; }
    else       { s = e - E; d = e - E; }
}
__device__ __forceinline__ void red_add_v4(float* addr, float a, float b, float c, float d) {
    asm volatile("red.global.add.v4.f32 [%0], {%1,%2,%3,%4};"
                 :: "l"(addr), "f"(a), "f"(b), "f"(c), "f"(d) : "memory");
}
__device__ __forceinline__ void red_add_v2(float* addr, float a, float b) {
    asm volatile("red.global.add.v2.f32 [%0], {%1,%2};"
                 :: "l"(addr), "f"(a), "f"(b) : "memory");
}
__device__ __forceinline__ uint32_t smem_u32(const void* p) {
    uint32_t a;
    asm("{ .reg .u64 t; cvta.to.shared.u64 t, %1; cvt.u32.u64 %0, t; }" : "=r"(a) : "l"(p));
    return a;
}
// pack two floats -> bf16x2: first arg to UPPER half, second to LOWER half
__device__ __forceinline__ uint32_t pack_bf16x2(float h, float l) {
    uint32_t r;
    asm("cvt.rn.bf16x2.f32 %0, %1, %2;" : "=r"(r) : "f"(h), "f"(l));
    return r;
}
__device__ __forceinline__ void ldsm4(uint32_t& r0, uint32_t& r1, uint32_t& r2,
                                      uint32_t& r3, uint32_t addr) {
    asm volatile("ldmatrix.sync.aligned.m8n8.x4.shared.b16 {%0,%1,%2,%3}, [%4];"
                 : "=r"(r0), "=r"(r1), "=r"(r2), "=r"(r3) : "r"(addr));
}
__device__ __forceinline__ void mma16816(float* d, uint32_t a0, uint32_t a1,
                                         uint32_t a2, uint32_t a3,
                                         uint32_t b0, uint32_t b1) {
    asm volatile("mma.sync.aligned.m16n8k16.row.col.f32.bf16.bf16.f32 "
                 "{%0,%1,%2,%3}, {%4,%5,%6,%7}, {%8,%9}, {%0,%1,%2,%3};"
                 : "+f"(d[0]), "+f"(d[1]), "+f"(d[2]), "+f"(d[3])
                 : "r"(a0), "r"(a1), "r"(a2), "r"(a3), "r"(b0), "r"(b1));
}
__device__ __forceinline__ void cp16(uint32_t smaddr, const void* gptr) {
    asm volatile("cp.async.cg.shared.global [%0], [%1], 16;"
                 :: "r"(smaddr), "l"(gptr) : "memory");
}
// split fp32 pair -> bf16x2 (hi = truncation, lo = RN residual)
__device__ __forceinline__ void cvt_split(float2 v, uint32_t& hi, uint32_t& lo) {
    uint32_t vx = __float_as_uint(v.x), vy = __float_as_uint(v.y);
    hi = __byte_perm(vx, vy, 0x7632);      // low half = bf16_trunc(v.x), high = v.y
    float hx = __uint_as_float(vx & 0xFFFF0000u);
    float hy = __uint_as_float(vy & 0xFFFF0000u);
    lo = pack_bf16x2(v.y - hy, v.x - hx);
}

// ---------------- init (float4 stores) ----------------
__global__ void k_init_all() {
    int i = blockIdx.x * blockDim.x + threadIdx.x;   // float4 index
    float4 z = make_float4(0.f, 0.f, 0.f, 0.f);
    if (i < NN * D1 / 4)    ((float4*)g_out1)[i] = z;
    if (i < NN * NCP / 4)   ((float4*)g_out2)[i] = z;
    if (i < NN * HEADS / 4) ((float4*)g_sum1)[i] = z;
    if (i < NN / 4)         ((float4*)g_sum2)[i] = z;
}

// ---------------- probe: no-op launch so k_gemm1 is the 4th launch (ncu) ---
__global__ void k_probe() {}

// ---------------- prep: transpose + bf16-split weights -------------------
__global__ void k_prep_w(const float* __restrict__ w1, const float* __restrict__ wres) {
    int idx = blockIdx.x * blockDim.x + threadIdx.x;
    if (idx >= 128 * KPAD) return;
    int n = idx >> 11;
    int k = idx & (KPAD - 1);
    float v = 0.f;
    if (k < NF) v = (n < 64) ? w1[(size_t)k * 64 + n] : wres[(size_t)k * 64 + (n - 64)];
    __nv_bfloat16 hi = __float2bfloat16(v);
    float rem = v - __bfloat162float(hi);
    __nv_bfloat16 lo = __float2bfloat16(rem);
    g_wt_hi[idx] = __bfloat16_as_ushort(hi);
    g_wt_lo[idx] = __bfloat16_as_ushort(lo);
}

// ---------------- GEMM1 via mma.sync bf16x3 + fused att1 ------------------
// [h1 | res] = x @ [w1 | wres]; as1/ad1 computed in-epilogue via quad shfl.
// 256 threads = 8 warps; warp w owns rows mbase+w*16. BK=32, 63 chunks.
// A prefetch 2 s-steps (32 k) deep to cover DRAM latency.
// D = Ahi*Bhi + Ahi*Blo + Alo*Bhi  (bf16x3; rel err ~1e-5)
#define NCH 63

__global__ __launch_bounds__(256, 2) void k_gemm1(const float* __restrict__ x,
                                                  const float* __restrict__ bres,
                                                  const float* __restrict__ asrc,
                                                  const float* __restrict__ adst) {
    __shared__ __align__(1024) unsigned char Bsm[32768]; // HI:0/8192, LO:16384/24576

    const int tid = threadIdx.x, wid = tid >> 5, lane = tid & 31;
    const int g = lane >> 2, c4 = lane & 3;
    const int mbase = blockIdx.x * 128 + wid * 16;
    int r0 = mbase + g;      if (r0 >= NN) r0 = NN - 1;
    int r1 = mbase + g + 8;  if (r1 >= NN) r1 = NN - 1;
    const uint32_t sb = smem_u32(Bsm);

    // ldmatrix per-lane constants
    const int nL   = (lane & 7) | ((lane & 16) >> 1);  // 0..15
    const int cbit = (lane >> 3) & 1;
    const int q    = cbit ^ ((nL >> 1) & 3);
    const uint32_t lrow = (uint32_t)(nL * 64);

    // cp.async per-thread dest offsets (2 chunks of 16B per split)
    const int fn0 = tid >> 2, fc0 = tid & 3;
    const int fn1 = (tid + 256) >> 2, fc1 = (tid + 256) & 3;
    const uint32_t fd0 = (uint32_t)(fn0 * 64 + ((fc0 ^ ((fn0 >> 1) & 3)) << 4));
    const uint32_t fd1 = (uint32_t)(fn1 * 64 + ((fc1 ^ ((fn1 >> 1) & 3)) << 4));

    float acc[16][4];
#pragma unroll
    for (int i = 0; i < 16; i++)
#pragma unroll
        for (int j = 0; j < 4; j++) acc[i][j] = 0.f;

    // ---- fill B chunk 0 ----
    {
        const char* sh0 = (const char*)&g_wt_hi[(size_t)fn0 * KPAD + fc0 * 8];
        const char* sh1 = (const char*)&g_wt_hi[(size_t)fn1 * KPAD + fc1 * 8];
        const char* sl0 = (const char*)&g_wt_lo[(size_t)fn0 * KPAD + fc0 * 8];
        const char* sl1 = (const char*)&g_wt_lo[(size_t)fn1 * KPAD + fc1 * 8];
        cp16(sb + fd0, sh0);             cp16(sb + fd1, sh1);
        cp16(sb + 16384 + fd0, sl0);     cp16(sb + 16384 + fd1, sl1);
        asm volatile("cp.async.commit_group;");
        asm volatile("cp.async.wait_group 0;");
    }
    __syncthreads();

    // A prefetch ring, 2 s-steps deep (t and t+1 resident)
    const int kc = 2 * c4;   // 0,2,4,6
    float2 abuf[2][4];
#pragma unroll
    for (int t0 = 0; t0 < 2; t0++) {
        int col = t0 * 16 + kc;
        abuf[t0][0] = *(const float2*)&x[(size_t)r0 * NF + col];
        abuf[t0][1] = *(const float2*)&x[(size_t)r1 * NF + col];
        abuf[t0][2] = *(const float2*)&x[(size_t)r0 * NF + col + 8];
        abuf[t0][3] = *(const float2*)&x[(size_t)r1 * NF + col + 8];
    }

    for (int c = 0; c < NCH; c++) {
        const uint32_t buf = (uint32_t)(c & 1) * 8192u;
        if (c + 1 < NCH) {
            const uint32_t nbuf = (uint32_t)((c + 1) & 1) * 8192u;
            size_t koff = (size_t)(c + 1) * 32;
            const char* sh0 = (const char*)&g_wt_hi[(size_t)fn0 * KPAD + koff + fc0 * 8];
            const char* sh1 = (const char*)&g_wt_hi[(size_t)fn1 * KPAD + koff + fc1 * 8];
            const char* sl0 = (const char*)&g_wt_lo[(size_t)fn0 * KPAD + koff + fc0 * 8];
            const char* sl1 = (const char*)&g_wt_lo[(size_t)fn1 * KPAD + koff + fc1 * 8];
            cp16(sb + nbuf + fd0, sh0);          cp16(sb + nbuf + fd1, sh1);
            cp16(sb + 16384 + nbuf + fd0, sl0);  cp16(sb + 16384 + nbuf + fd1, sl1);
            asm volatile("cp.async.commit_group;");
        }
#pragma unroll
        for (int s = 0; s < 2; s++) {
            const int t = c * 2 + s;
            const int slot = t & 1;
            // convert current A -> hi/lo fragments
            uint32_t ah[4], al[4];
#pragma unroll
            for (int i = 0; i < 4; i++) cvt_split(abuf[slot][i], ah[i], al[i]);

            // prefetch t+2 into the slot just consumed (2-step distance)
            {
                int ncol = (t + 2) * 16 + kc;
                bool p0 = ncol < NF, p1 = (ncol + 8) < NF;
                abuf[slot][0] = p0 ? *(const float2*)&x[(size_t)r0 * NF + ncol] : make_float2(0.f, 0.f);
                abuf[slot][1] = p0 ? *(const float2*)&x[(size_t)r1 * NF + ncol] : make_float2(0.f, 0.f);
                abuf[slot][2] = p1 ? *(const float2*)&x[(size_t)r0 * NF + ncol + 8] : make_float2(0.f, 0.f);
                abuf[slot][3] = p1 ? *(const float2*)&x[(size_t)r1 * NF + ncol + 8] : make_float2(0.f, 0.f);
            }

            const uint32_t loff = lrow + ((uint32_t)(q ^ (s << 1)) << 4);
#pragma unroll
            for (int nb = 0; nb < 8; nb++) {
                uint32_t addr = sb + buf + (uint32_t)(nb * 1024) + loff;
                uint32_t h0, h1, h2, h3, l0, l1, l2, l3;
                ldsm4(h0, h1, h2, h3, addr);
                ldsm4(l0, l1, l2, l3, addr + 16384u);
                float* d0 = acc[nb * 2];
                float* d1 = acc[nb * 2 + 1];
                mma16816(d0, ah[0], ah[1], ah[2], ah[3], h0, h1);
                mma16816(d0, ah[0], ah[1], ah[2], ah[3], l0, l1);
                mma16816(d0, al[0], al[1], al[2], al[3], h0, h1);
                mma16816(d1, ah[0], ah[1], ah[2], ah[3], h2, h3);
                mma16816(d1, ah[0], ah[1], ah[2], ah[3], l2, l3);
                mma16816(d1, al[0], al[1], al[2], al[3], h2, h3);
            }
        }
        if (c + 1 < NCH) {
            asm volatile("cp.async.wait_group 0;");
            __syncthreads();
        }
    }

    // ---- epilogue: store h1/res ----
    int row0 = mbase + g, row1 = mbase + g + 8;
#pragma unroll
    for (int nf = 0; nf < 16; nf++) {
        int col = nf * 8 + 2 * c4;
        float2 v0 = make_float2(acc[nf][0], acc[nf][1]);
        float2 v1 = make_float2(acc[nf][2], acc[nf][3]);
        if (col < 64) {
            if (row0 < NN) *(float2*)&g_h1[(size_t)row0 * 64 + col] = v0;
            if (row1 < NN) *(float2*)&g_h1[(size_t)row1 * 64 + col] = v1;
        } else {
            int nr = col - 64;
            float b0 = __ldg(&bres[nr]), b1 = __ldg(&bres[nr + 1]);
            v0.x += b0; v0.y += b1; v1.x += b0; v1.y += b1;
            if (row0 < NN) *(float2*)&g_res[(size_t)row0 * 64 + nr] = v0;
            if (row1 < NN) *(float2*)&g_res[(size_t)row1 * 64 + nr] = v1;
        }
    }

    // ---- fused att1: head h = nf (cols nf*8..nf*8+7), quad-reduce over c4 --
#pragma unroll
    for (int nf = 0; nf < 8; nf++) {
        float ws0 = __ldg(&asrc[nf * 8 + 2 * c4]);
        float ws1 = __ldg(&asrc[nf * 8 + 2 * c4 + 1]);
        float wd0 = __ldg(&adst[nf * 8 + 2 * c4]);
        float wd1 = __ldg(&adst[nf * 8 + 2 * c4 + 1]);
        float ps0 = acc[nf][0] * ws0 + acc[nf][1] * ws1;
        float pd0 = acc[nf][0] * wd0 + acc[nf][1] * wd1;
        float ps1 = acc[nf][2] * ws0 + acc[nf][3] * ws1;
        float pd1 = acc[nf][2] * wd0 + acc[nf][3] * wd1;
        ps0 += __shfl_xor_sync(0xffffffffu, ps0, 1);
        ps0 += __shfl_xor_sync(0xffffffffu, ps0, 2);
        pd0 += __shfl_xor_sync(0xffffffffu, pd0, 1);
        pd0 += __shfl_xor_sync(0xffffffffu, pd0, 2);
        ps1 += __shfl_xor_sync(0xffffffffu, ps1, 1);
        ps1 += __shfl_xor_sync(0xffffffffu, ps1, 2);
        pd1 += __shfl_xor_sync(0xffffffffu, pd1, 1);
        pd1 += __shfl_xor_sync(0xffffffffu, pd1, 2);
        if (c4 == 0) {
            if (row0 < NN) { g_as1[row0 * 8 + nf] = ps0; g_ad1[row0 * 8 + nf] = pd0; }
            if (row1 < NN) { g_as1[row1 * 8 + nf] = ps1; g_ad1[row1 * 8 + nf] = pd1; }
        }
    }
}

// ---------------- edge pass 1a: exp + store + sum ----------------
__global__ void k_esum1(const int* __restrict__ ei, int E, int Etot) {
    int e = blockIdx.x * blockDim.x + threadIdx.x;
    if (e >= Etot) return;
    int s, d; edge_sd(ei, E, e, s, d);
    float4 s0 = *(const float4*)&g_as1[s * 8];
    float4 s1 = *(const float4*)&g_as1[s * 8 + 4];
    float4 d0 = *(const float4*)&g_ad1[d * 8];
    float4 d1 = *(const float4*)&g_ad1[d * 8 + 4];
    float v[8] = {s0.x + d0.x, s0.y + d0.y, s0.z + d0.z, s0.w + d0.w,
                  s1.x + d1.x, s1.y + d1.y, s1.z + d1.z, s1.w + d1.w};
    float ev[8];
#pragma unroll
    for (int h = 0; h < 8; h++) {
        float t = (v[h] > 0.f) ? v[h] : 0.2f * v[h];
        ev[h] = __expf(t);
    }
    *(float4*)&g_eb1[(size_t)e * 8]     = make_float4(ev[0], ev[1], ev[2], ev[3]);
    *(float4*)&g_eb1[(size_t)e * 8 + 4] = make_float4(ev[4], ev[5], ev[6], ev[7]);
    red_add_v4(&g_sum1[d * 8],     ev[0], ev[1], ev[2], ev[3]);
    red_add_v4(&g_sum1[d * 8 + 4], ev[4], ev[5], ev[6], ev[7]);
}

// ---------------- edge pass 1b: alpha + message scatter --------------------
__global__ void k_emsg1(const int* __restrict__ ei, int E, int Etot,
                        float* __restrict__ a1out) {
    int e = blockIdx.x * blockDim.x + threadIdx.x;
    if (e >= Etot) return;
    int s, d; edge_sd(ei, E, e, s, d);
    float4 e0 = *(const float4*)&g_eb1[(size_t)e * 8];
    float4 e1 = *(const float4*)&g_eb1[(size_t)e * 8 + 4];
    float4 q0 = *(const float4*)&g_sum1[d * 8];
    float4 q1 = *(const float4*)&g_sum1[d * 8 + 4];
    float alpha[8] = {e0.x / (q0.x + 1e-16f), e0.y / (q0.y + 1e-16f),
                      e0.z / (q0.z + 1e-16f), e0.w / (q0.w + 1e-16f),
                      e1.x / (q1.x + 1e-16f), e1.y / (q1.y + 1e-16f),
                      e1.z / (q1.z + 1e-16f), e1.w / (q1.w + 1e-16f)};
    if (a1out) {
        *(float4*)&a1out[(size_t)e * 8]     = make_float4(alpha[0], alpha[1], alpha[2], alpha[3]);
        *(float4*)&a1out[(size_t)e * 8 + 4] = make_float4(alpha[4], alpha[5], alpha[6], alpha[7]);
    }
    const float* hr = &g_h1[(size_t)s * 64];
    float* o = &g_out1[(size_t)d * 64];
#pragma unroll
    for (int h = 0; h < 8; h++) {
        float a = alpha[h];
        float4 h0 = *(const float4*)&hr[h * 8];
        float4 h1v = *(const float4*)&hr[h * 8 + 4];
        red_add_v4(o + h * 8,     h0.x * a, h0.y * a, h0.z * a, h0.w * a);
        red_add_v4(o + h * 8 + 4, h1v.x * a, h1v.y * a, h1v.z * a, h1v.w * a);
    }
}

// ---------------- GEMM2 (+ fused x1 elu) + att2 coefficients ---------------
__global__ __launch_bounds__(128) void k_gemm2(const float* __restrict__ w2,
                                               const float* __restrict__ watt_s,
                                               const float* __restrict__ watt_d,
                                               const float* __restrict__ b1) {
    __shared__ float sw[64 * NC];
    __shared__ float ss[NC], sd[NC];
    __shared__ float sb1[64];
    int tid = threadIdx.x;
    for (int i = tid; i < 64 * NC; i += blockDim.x) sw[i] = w2[i];
    if (tid < NC) { ss[tid] = watt_s[tid]; sd[tid] = watt_d[tid]; }
    if (tid < 64) sb1[tid] = b1[tid];
    __syncthreads();
    int n = blockIdx.x * blockDim.x + tid;
    if (n >= NN) return;
    float r[64];
    const float4* orow = (const float4*)&g_out1[(size_t)n * 64];
    const float4* rrow = (const float4*)&g_res[(size_t)n * 64];
#pragma unroll
    for (int i = 0; i < 16; i++) {
        float4 o = orow[i];
        float4 rr = rrow[i];
        float t0 = o.x + sb1[i * 4 + 0] + rr.x;
        float t1 = o.y + sb1[i * 4 + 1] + rr.y;
        float t2 = o.z + sb1[i * 4 + 2] + rr.z;
        float t3 = o.w + sb1[i * 4 + 3] + rr.w;
        r[i * 4 + 0] = (t0 > 0.f) ? t0 : expm1f(t0);
        r[i * 4 + 1] = (t1 > 0.f) ? t1 : expm1f(t1);
        r[i * 4 + 2] = (t2 > 0.f) ? t2 : expm1f(t2);
        r[i * 4 + 3] = (t3 > 0.f) ? t3 : expm1f(t3);
    }
    float as = 0.f, ad = 0.f;
#pragma unroll
    for (int j = 0; j < NC; j++) {
        float sacc = 0.f;
#pragma unroll
        for (int k = 0; k < 64; k++) sacc += r[k] * sw[k * NC + j];
        g_h2[(size_t)n * NCP + j] = sacc;
        as += sacc * ss[j];
        ad += sacc * sd[j];
    }
    g_as2[n] = as;
    g_ad2[n] = ad;
}

// ---------------- edge passes layer 2 (H=1, C=30; store model) -------------
__global__ void k_esum2(const int* __restrict__ ei, int E, int Etot) {
    int e = blockIdx.x * blockDim.x + threadIdx.x;
    if (e >= Etot) return;
    int s, d; edge_sd(ei, E, e, s, d);
    float v = g_as2[s] + g_ad2[d];
    v = (v > 0.f) ? v : 0.2f * v;
    float ev = __expf(v);
    g_eb2[e] = ev;
    atomicAdd(&g_sum2[d], ev);
}

__global__ void k_emsg2(const int* __restrict__ ei, int E, int Etot,
                        float* __restrict__ a2out) {
    int e = blockIdx.x * blockDim.x + threadIdx.x;
    if (e >= Etot) return;
    int s, d; edge_sd(ei, E, e, s, d);
    float alpha = g_eb2[e] / (g_sum2[d] + 1e-16f);
    if (a2out) a2out[e] = alpha;
    const float4* hp = (const float4*)&g_h2[(size_t)s * NCP];
    float* op = &g_out2[(size_t)d * NCP];
#pragma unroll
    for (int q = 0; q < 7; q++) {
        float4 vv = hp[q];
        red_add_v4(op + q * 4, vv.x * alpha, vv.y * alpha, vv.z * alpha, vv.w * alpha);
    }
    float2 t = *(const float2*)&g_h2[(size_t)s * NCP + 28];
    red_add_v2(op + 28, t.x * alpha, t.y * alpha);
}

// ---------------- final: elu(out2 + b2), log_softmax (float4 loads) --------
__global__ void k_final(const float* __restrict__ b2, float* __restrict__ out) {
    int n = blockIdx.x * blockDim.x + threadIdx.x;
    if (n >= NN) return;
    float v[NC];
    const float4* row = (const float4*)&g_out2[(size_t)n * NCP];
    float m = -INFINITY;
#pragma unroll
    for (int qi = 0; qi < 8; qi++) {
        float4 w = row[qi];
        int base = qi * 4;
        float tv[4] = {w.x, w.y, w.z, w.w};
#pragma unroll
        for (int j = 0; j < 4; j++) {
            int c = base + j;
            if (c < NC) {
                float t = tv[j] + __ldg(&b2[c]);
                t = (t > 0.f) ? t : expm1f(t);
                v[c] = t;
                m = fmaxf(m, t);
            }
        }
    }
    float ssum = 0.f;
#pragma unroll
    for (int c = 0; c < NC; c++) ssum += expf(v[c] - m);
    float lse = m + logf(ssum);
#pragma unroll
    for (int c = 0; c < NC; c++) out[(size_t)n * NC + c] = v[c] - lse;
}

// ---------------- launch ----------------
extern "C" void kernel_launch(void* const* d_in, const int* in_sizes, int n_in,
                              void* d_out, int out_size) {
    const float* x      = (const float*)d_in[0];
    const int*   ei     = (const int*)d_in[1];
    const float* w_res  = (const float*)d_in[2];
    const float* b_res  = (const float*)d_in[3];
    const float* w1     = (const float*)d_in[4];
    const float* att_s1 = (const float*)d_in[5];
    const float* att_d1 = (const float*)d_in[6];
    const float* b1     = (const float*)d_in[7];
    const float* w2     = (const float*)d_in[8];
    const float* att_s2 = (const float*)d_in[9];
    const float* att_d2 = (const float*)d_in[10];
    const float* b2     = (const float*)d_in[11];

    int E = in_sizes[1] / 2;
    int Etot = E + NN;

    float* out = (float*)d_out;
    long long need = (long long)NN * NC + (long long)Etot * HEADS + (long long)Etot;
    float *a1out = nullptr, *a2out = nullptr;
    if ((long long)out_size >= need) {
        a1out = out + (size_t)NN * NC;
        a2out = a1out + (size_t)Etot * HEADS;
    }

    k_init_all<<<(NN * D1 / 4 + 255) / 256, 256>>>();
    k_prep_w<<<(128 * KPAD + 255) / 256, 256>>>(w1, w_res);
    k_probe<<<1, 32>>>();   // positions k_gemm1 as 4th launch for ncu capture
    k_gemm1<<<(NN + 127) / 128, 256>>>(x, b_res, att_s1, att_d1);

    k_esum1<<<(Etot + 255) / 256, 256>>>(ei, E, Etot);
    k_emsg1<<<(Etot + 255) / 256, 256>>>(ei, E, Etot, a1out);

    k_gemm2<<<(NN + 127) / 128, 128>>>(w2, att_s2, att_d2, b1);

    k_esum2<<<(Etot + 255) / 256, 256>>>(ei, E, Etot);
    k_emsg2<<<(Etot + 255) / 256, 256>>>(ei, E, Etot, a2out);

    k_final<<<(NN + 127) / 128, 128>>>(b2, out);
}

// round 16
// speedup vs baseline: 1.1890x; 1.0473x over previous
#include <cuda_runtime.h>
#include <cuda_bf16.h>
#include <math.h>
#include <stdint.h>

// Problem constants (fixed shapes per reference)
#define NN    50000
#define NF    2000
#define KPAD  2048
#define D1    64
#define HEADS 8
#define HID   8
#define NC    30
#define NCP   32
#define MAXET 1700000

// ---------------- scratch (device globals; no allocation allowed) ----------
__device__ float g_h1[(size_t)NN * D1];
__device__ float g_res[(size_t)NN * D1];
__device__ float g_as1[NN * HEADS];
__device__ float g_ad1[NN * HEADS];
__device__ float g_sum1[NN * HEADS];
__device__ float g_eb1[(size_t)MAXET * HEADS];
__device__ float g_out1[(size_t)NN * D1];
__device__ float g_h2[(size_t)NN * NCP];
__device__ float g_as2[NN];
__device__ float g_ad2[NN];
__device__ float g_sum2[NN];
__device__ float g_eb2[MAXET];
__device__ float g_out2[(size_t)NN * NCP];
// pre-transposed + split weights: [n=0..127][k=0..2047] bf16 (zeros past NF)
__device__ unsigned short g_wt_hi[128 * KPAD];
__device__ unsigned short g_wt_lo[128 * KPAD];

// ---------------- helpers ----------------
__device__ __forceinline__ void edge_sd(const int* __restrict__ ei, int E, int e,
                                        int& s, int& d) {
    if (e < E) { s = ei[e]; d = ei[E + e]; }
    else       { s = e - E; d = e - E; }
}
__device__ __forceinline__ void red_add_v4(float* addr, float a, float b, float c, float d) {
    asm volatile("red.global.add.v4.f32 [%0], {%1,%2,%3,%4};"
                 :: "l"(addr), "f"(a), "f"(b), "f"(c), "f"(d) : "memory");
}
__device__ __forceinline__ void red_add_v2(float* addr, float a, float b) {
    asm volatile("red.global.add.v2.f32 [%0], {%1,%2};"
                 :: "l"(addr), "f"(a), "f"(b) : "memory");
}
__device__ __forceinline__ uint32_t smem_u32(const void* p) {
    uint32_t a;
    asm("{ .reg .u64 t; cvta.to.shared.u64 t, %1; cvt.u32.u64 %0, t; }" : "=r"(a) : "l"(p));
    return a;
}
// pack two floats -> bf16x2: first arg to UPPER half, second to LOWER half
__device__ __forceinline__ uint32_t pack_bf16x2(float h, float l) {
    uint32_t r;
    asm("cvt.rn.bf16x2.f32 %0, %1, %2;" : "=r"(r) : "f"(h), "f"(l));
    return r;
}
__device__ __forceinline__ void ldsm4(uint32_t& r0, uint32_t& r1, uint32_t& r2,
                                      uint32_t& r3, uint32_t addr) {
    asm volatile("ldmatrix.sync.aligned.m8n8.x4.shared.b16 {%0,%1,%2,%3}, [%4];"
                 : "=r"(r0), "=r"(r1), "=r"(r2), "=r"(r3) : "r"(addr));
}
__device__ __forceinline__ void mma16816(float* d, uint32_t a0, uint32_t a1,
                                         uint32_t a2, uint32_t a3,
                                         uint32_t b0, uint32_t b1) {
    asm volatile("mma.sync.aligned.m16n8k16.row.col.f32.bf16.bf16.f32 "
                 "{%0,%1,%2,%3}, {%4,%5,%6,%7}, {%8,%9}, {%0,%1,%2,%3};"
                 : "+f"(d[0]), "+f"(d[1]), "+f"(d[2]), "+f"(d[3])
                 : "r"(a0), "r"(a1), "r"(a2), "r"(a3), "r"(b0), "r"(b1));
}
__device__ __forceinline__ void cp16(uint32_t smaddr, const void* gptr) {
    asm volatile("cp.async.cg.shared.global [%0], [%1], 16;"
                 :: "r"(smaddr), "l"(gptr) : "memory");
}
// split fp32 pair -> bf16x2 (hi = truncation, lo = RN residual)
__device__ __forceinline__ void cvt_split(float2 v, uint32_t& hi, uint32_t& lo) {
    uint32_t vx = __float_as_uint(v.x), vy = __float_as_uint(v.y);
    hi = __byte_perm(vx, vy, 0x7632);      // low half = bf16_trunc(v.x), high = v.y
    float hx = __uint_as_float(vx & 0xFFFF0000u);
    float hy = __uint_as_float(vy & 0xFFFF0000u);
    lo = pack_bf16x2(v.y - hy, v.x - hx);
}

// ---------------- fused init + weight prep ----------------
__global__ void k_initprep(const float* __restrict__ w1, const float* __restrict__ wres) {
    int i = blockIdx.x * blockDim.x + threadIdx.x;
    if (i < 128 * KPAD) {
        int n = i >> 11;
        int k = i & (KPAD - 1);
        float v = 0.f;
        if (k < NF) v = (n < 64) ? w1[(size_t)k * 64 + n] : wres[(size_t)k * 64 + (n - 64)];
        __nv_bfloat16 hi = __float2bfloat16(v);
        float rem = v - __bfloat162float(hi);
        __nv_bfloat16 lo = __float2bfloat16(rem);
        g_wt_hi[i] = __bfloat16_as_ushort(hi);
        g_wt_lo[i] = __bfloat16_as_ushort(lo);
    }
    float4 z = make_float4(0.f, 0.f, 0.f, 0.f);
    if (i < NN * D1 / 4)    ((float4*)g_out1)[i] = z;
    if (i < NN * NCP / 4)   ((float4*)g_out2)[i] = z;
    if (i < NN * HEADS / 4) ((float4*)g_sum1)[i] = z;
    if (i < NN / 4)         ((float4*)g_sum2)[i] = z;
}

// ---------------- GEMM1 via mma.sync bf16x3 + fused att1 ------------------
// [h1 | res] = x @ [w1 | wres]; as1/ad1 computed in-epilogue via quad shfl.
// 256 threads = 8 warps; warp w owns rows mbase+w*16. BK=32, 63 chunks.
// A prefetch 2 s-steps deep; bh (hi-B) fragments double-buffered across nb,
// bl loaded just-in-time (register-pressure compromise).
// D = Ahi*Bhi + Ahi*Blo + Alo*Bhi  (bf16x3; rel err ~1e-5)
#define NCH 63

__global__ __launch_bounds__(256, 2) void k_gemm1(const float* __restrict__ x,
                                                  const float* __restrict__ bres,
                                                  const float* __restrict__ asrc,
                                                  const float* __restrict__ adst) {
    __shared__ __align__(1024) unsigned char Bsm[32768]; // HI:0/8192, LO:16384/24576

    const int tid = threadIdx.x, wid = tid >> 5, lane = tid & 31;
    const int g = lane >> 2, c4 = lane & 3;
    const int mbase = blockIdx.x * 128 + wid * 16;
    int r0 = mbase + g;      if (r0 >= NN) r0 = NN - 1;
    int r1 = mbase + g + 8;  if (r1 >= NN) r1 = NN - 1;
    const uint32_t sb = smem_u32(Bsm);

    // ldmatrix per-lane constants
    const int nL   = (lane & 7) | ((lane & 16) >> 1);  // 0..15
    const int cbit = (lane >> 3) & 1;
    const int q    = cbit ^ ((nL >> 1) & 3);
    const uint32_t lrow = (uint32_t)(nL * 64);

    // cp.async per-thread dest offsets (2 chunks of 16B per split)
    const int fn0 = tid >> 2, fc0 = tid & 3;
    const int fn1 = (tid + 256) >> 2, fc1 = (tid + 256) & 3;
    const uint32_t fd0 = (uint32_t)(fn0 * 64 + ((fc0 ^ ((fn0 >> 1) & 3)) << 4));
    const uint32_t fd1 = (uint32_t)(fn1 * 64 + ((fc1 ^ ((fn1 >> 1) & 3)) << 4));

    float acc[16][4];
#pragma unroll
    for (int i = 0; i < 16; i++)
#pragma unroll
        for (int j = 0; j < 4; j++) acc[i][j] = 0.f;

    // ---- fill B chunk 0 ----
    {
        const char* sh0 = (const char*)&g_wt_hi[(size_t)fn0 * KPAD + fc0 * 8];
        const char* sh1 = (const char*)&g_wt_hi[(size_t)fn1 * KPAD + fc1 * 8];
        const char* sl0 = (const char*)&g_wt_lo[(size_t)fn0 * KPAD + fc0 * 8];
        const char* sl1 = (const char*)&g_wt_lo[(size_t)fn1 * KPAD + fc1 * 8];
        cp16(sb + fd0, sh0);             cp16(sb + fd1, sh1);
        cp16(sb + 16384 + fd0, sl0);     cp16(sb + 16384 + fd1, sl1);
        asm volatile("cp.async.commit_group;");
        asm volatile("cp.async.wait_group 0;");
    }
    __syncthreads();

    // A prefetch ring, 2 s-steps deep (t and t+1 resident)
    const int kc = 2 * c4;   // 0,2,4,6
    float2 abuf[2][4];
#pragma unroll
    for (int t0 = 0; t0 < 2; t0++) {
        int col = t0 * 16 + kc;
        abuf[t0][0] = *(const float2*)&x[(size_t)r0 * NF + col];
        abuf[t0][1] = *(const float2*)&x[(size_t)r1 * NF + col];
        abuf[t0][2] = *(const float2*)&x[(size_t)r0 * NF + col + 8];
        abuf[t0][3] = *(const float2*)&x[(size_t)r1 * NF + col + 8];
    }

    for (int c = 0; c < NCH; c++) {
        const uint32_t buf = (uint32_t)(c & 1) * 8192u;
        if (c + 1 < NCH) {
            const uint32_t nbuf = (uint32_t)((c + 1) & 1) * 8192u;
            size_t koff = (size_t)(c + 1) * 32;
            const char* sh0 = (const char*)&g_wt_hi[(size_t)fn0 * KPAD + koff + fc0 * 8];
            const char* sh1 = (const char*)&g_wt_hi[(size_t)fn1 * KPAD + koff + fc1 * 8];
            const char* sl0 = (const char*)&g_wt_lo[(size_t)fn0 * KPAD + koff + fc0 * 8];
            const char* sl1 = (const char*)&g_wt_lo[(size_t)fn1 * KPAD + koff + fc1 * 8];
            cp16(sb + nbuf + fd0, sh0);          cp16(sb + nbuf + fd1, sh1);
            cp16(sb + 16384 + nbuf + fd0, sl0);  cp16(sb + 16384 + nbuf + fd1, sl1);
            asm volatile("cp.async.commit_group;");
        }
#pragma unroll
        for (int s = 0; s < 2; s++) {
            const int t = c * 2 + s;
            const int slot = t & 1;
            // convert current A -> hi/lo fragments
            uint32_t ah[4], al[4];
#pragma unroll
            for (int i = 0; i < 4; i++) cvt_split(abuf[slot][i], ah[i], al[i]);

            // prefetch t+2 into the slot just consumed (2-step distance)
            {
                int ncol = (t + 2) * 16 + kc;
                bool p0 = ncol < NF, p1 = (ncol + 8) < NF;
                abuf[slot][0] = p0 ? *(const float2*)&x[(size_t)r0 * NF + ncol] : make_float2(0.f, 0.f);
                abuf[slot][1] = p0 ? *(const float2*)&x[(size_t)r1 * NF + ncol] : make_float2(0.f, 0.f);
                abuf[slot][2] = p1 ? *(const float2*)&x[(size_t)r0 * NF + ncol + 8] : make_float2(0.f, 0.f);
                abuf[slot][3] = p1 ? *(const float2*)&x[(size_t)r1 * NF + ncol + 8] : make_float2(0.f, 0.f);
            }

            const uint32_t loff = lrow + ((uint32_t)(q ^ (s << 1)) << 4);
            // bh double-buffered across nb; bl loaded just-in-time
            uint32_t bh[2][4];
            {
                uint32_t a0 = sb + buf + loff;
                ldsm4(bh[0][0], bh[0][1], bh[0][2], bh[0][3], a0);
            }
#pragma unroll
            for (int nb = 0; nb < 8; nb++) {
                const int cur = nb & 1, nxt = cur ^ 1;
                uint32_t bl0, bl1, bl2, bl3;
                ldsm4(bl0, bl1, bl2, bl3,
                      sb + buf + (uint32_t)(nb * 1024) + loff + 16384u);
                if (nb < 7) {
                    uint32_t an = sb + buf + (uint32_t)((nb + 1) * 1024) + loff;
                    ldsm4(bh[nxt][0], bh[nxt][1], bh[nxt][2], bh[nxt][3], an);
                }
                float* d0 = acc[nb * 2];
                float* d1 = acc[nb * 2 + 1];
                mma16816(d0, ah[0], ah[1], ah[2], ah[3], bh[cur][0], bh[cur][1]);
                mma16816(d0, al[0], al[1], al[2], al[3], bh[cur][0], bh[cur][1]);
                mma16816(d1, ah[0], ah[1], ah[2], ah[3], bh[cur][2], bh[cur][3]);
                mma16816(d1, al[0], al[1], al[2], al[3], bh[cur][2], bh[cur][3]);
                mma16816(d0, ah[0], ah[1], ah[2], ah[3], bl0, bl1);
                mma16816(d1, ah[0], ah[1], ah[2], ah[3], bl2, bl3);
            }
        }
        if (c + 1 < NCH) {
            asm volatile("cp.async.wait_group 0;");
            __syncthreads();
        }
    }

    // ---- epilogue: store h1/res ----
    int row0 = mbase + g, row1 = mbase + g + 8;
#pragma unroll
    for (int nf = 0; nf < 16; nf++) {
        int col = nf * 8 + 2 * c4;
        float2 v0 = make_float2(acc[nf][0], acc[nf][1]);
        float2 v1 = make_float2(acc[nf][2], acc[nf][3]);
        if (col < 64) {
            if (row0 < NN) *(float2*)&g_h1[(size_t)row0 * 64 + col] = v0;
            if (row1 < NN) *(float2*)&g_h1[(size_t)row1 * 64 + col] = v1;
        } else {
            int nr = col - 64;
            float b0 = __ldg(&bres[nr]), b1 = __ldg(&bres[nr + 1]);
            v0.x += b0; v0.y += b1; v1.x += b0; v1.y += b1;
            if (row0 < NN) *(float2*)&g_res[(size_t)row0 * 64 + nr] = v0;
            if (row1 < NN) *(float2*)&g_res[(size_t)row1 * 64 + nr] = v1;
        }
    }

    // ---- fused att1: head h = nf (cols nf*8..nf*8+7), quad-reduce over c4 --
#pragma unroll
    for (int nf = 0; nf < 8; nf++) {
        float ws0 = __ldg(&asrc[nf * 8 + 2 * c4]);
        float ws1 = __ldg(&asrc[nf * 8 + 2 * c4 + 1]);
        float wd0 = __ldg(&adst[nf * 8 + 2 * c4]);
        float wd1 = __ldg(&adst[nf * 8 + 2 * c4 + 1]);
        float ps0 = acc[nf][0] * ws0 + acc[nf][1] * ws1;
        float pd0 = acc[nf][0] * wd0 + acc[nf][1] * wd1;
        float ps1 = acc[nf][2] * ws0 + acc[nf][3] * ws1;
        float pd1 = acc[nf][2] * wd0 + acc[nf][3] * wd1;
        ps0 += __shfl_xor_sync(0xffffffffu, ps0, 1);
        ps0 += __shfl_xor_sync(0xffffffffu, ps0, 2);
        pd0 += __shfl_xor_sync(0xffffffffu, pd0, 1);
        pd0 += __shfl_xor_sync(0xffffffffu, pd0, 2);
        ps1 += __shfl_xor_sync(0xffffffffu, ps1, 1);
        ps1 += __shfl_xor_sync(0xffffffffu, ps1, 2);
        pd1 += __shfl_xor_sync(0xffffffffu, pd1, 1);
        pd1 += __shfl_xor_sync(0xffffffffu, pd1, 2);
        if (c4 == 0) {
            if (row0 < NN) { g_as1[row0 * 8 + nf] = ps0; g_ad1[row0 * 8 + nf] = pd0; }
            if (row1 < NN) { g_as1[row1 * 8 + nf] = ps1; g_ad1[row1 * 8 + nf] = pd1; }
        }
    }
}

// ---------------- edge pass 1a: exp + store + sum ----------------
__global__ void k_esum1(const int* __restrict__ ei, int E, int Etot) {
    int e = blockIdx.x * blockDim.x + threadIdx.x;
    if (e >= Etot) return;
    int s, d; edge_sd(ei, E, e, s, d);
    float4 s0 = *(const float4*)&g_as1[s * 8];
    float4 s1 = *(const float4*)&g_as1[s * 8 + 4];
    float4 d0 = *(const float4*)&g_ad1[d * 8];
    float4 d1 = *(const float4*)&g_ad1[d * 8 + 4];
    float v[8] = {s0.x + d0.x, s0.y + d0.y, s0.z + d0.z, s0.w + d0.w,
                  s1.x + d1.x, s1.y + d1.y, s1.z + d1.z, s1.w + d1.w};
    float ev[8];
#pragma unroll
    for (int h = 0; h < 8; h++) {
        float t = (v[h] > 0.f) ? v[h] : 0.2f * v[h];
        ev[h] = __expf(t);
    }
    *(float4*)&g_eb1[(size_t)e * 8]     = make_float4(ev[0], ev[1], ev[2], ev[3]);
    *(float4*)&g_eb1[(size_t)e * 8 + 4] = make_float4(ev[4], ev[5], ev[6], ev[7]);
    red_add_v4(&g_sum1[d * 8],     ev[0], ev[1], ev[2], ev[3]);
    red_add_v4(&g_sum1[d * 8 + 4], ev[4], ev[5], ev[6], ev[7]);
}

// ---------------- edge pass 1b: alpha + message scatter --------------------
__global__ void k_emsg1(const int* __restrict__ ei, int E, int Etot,
                        float* __restrict__ a1out) {
    int e = blockIdx.x * blockDim.x + threadIdx.x;
    if (e >= Etot) return;
    int s, d; edge_sd(ei, E, e, s, d);
    float4 e0 = *(const float4*)&g_eb1[(size_t)e * 8];
    float4 e1 = *(const float4*)&g_eb1[(size_t)e * 8 + 4];
    float4 q0 = *(const float4*)&g_sum1[d * 8];
    float4 q1 = *(const float4*)&g_sum1[d * 8 + 4];
    float alpha[8] = {e0.x / (q0.x + 1e-16f), e0.y / (q0.y + 1e-16f),
                      e0.z / (q0.z + 1e-16f), e0.w / (q0.w + 1e-16f),
                      e1.x / (q1.x + 1e-16f), e1.y / (q1.y + 1e-16f),
                      e1.z / (q1.z + 1e-16f), e1.w / (q1.w + 1e-16f)};
    if (a1out) {
        *(float4*)&a1out[(size_t)e * 8]     = make_float4(alpha[0], alpha[1], alpha[2], alpha[3]);
        *(float4*)&a1out[(size_t)e * 8 + 4] = make_float4(alpha[4], alpha[5], alpha[6], alpha[7]);
    }
    const float* hr = &g_h1[(size_t)s * 64];
    float* o = &g_out1[(size_t)d * 64];
#pragma unroll
    for (int h = 0; h < 8; h++) {
        float a = alpha[h];
        float4 h0 = *(const float4*)&hr[h * 8];
        float4 h1v = *(const float4*)&hr[h * 8 + 4];
        red_add_v4(o + h * 8,     h0.x * a, h0.y * a, h0.z * a, h0.w * a);
        red_add_v4(o + h * 8 + 4, h1v.x * a, h1v.y * a, h1v.z * a, h1v.w * a);
    }
}

// ---------------- GEMM2 (+ fused x1 elu) + att2 coefficients ---------------
__global__ __launch_bounds__(128) void k_gemm2(const float* __restrict__ w2,
                                               const float* __restrict__ watt_s,
                                               const float* __restrict__ watt_d,
                                               const float* __restrict__ b1) {
    __shared__ float sw[64 * NC];
    __shared__ float ss[NC], sd[NC];
    __shared__ float sb1[64];
    int tid = threadIdx.x;
    for (int i = tid; i < 64 * NC; i += blockDim.x) sw[i] = w2[i];
    if (tid < NC) { ss[tid] = watt_s[tid]; sd[tid] = watt_d[tid]; }
    if (tid < 64) sb1[tid] = b1[tid];
    __syncthreads();
    int n = blockIdx.x * blockDim.x + tid;
    if (n >= NN) return;
    float r[64];
    const float4* orow = (const float4*)&g_out1[(size_t)n * 64];
    const float4* rrow = (const float4*)&g_res[(size_t)n * 64];
#pragma unroll
    for (int i = 0; i < 16; i++) {
        float4 o = orow[i];
        float4 rr = rrow[i];
        float t0 = o.x + sb1[i * 4 + 0] + rr.x;
        float t1 = o.y + sb1[i * 4 + 1] + rr.y;
        float t2 = o.z + sb1[i * 4 + 2] + rr.z;
        float t3 = o.w + sb1[i * 4 + 3] + rr.w;
        r[i * 4 + 0] = (t0 > 0.f) ? t0 : expm1f(t0);
        r[i * 4 + 1] = (t1 > 0.f) ? t1 : expm1f(t1);
        r[i * 4 + 2] = (t2 > 0.f) ? t2 : expm1f(t2);
        r[i * 4 + 3] = (t3 > 0.f) ? t3 : expm1f(t3);
    }
    float as = 0.f, ad = 0.f;
#pragma unroll
    for (int j = 0; j < NC; j++) {
        float sacc = 0.f;
#pragma unroll
        for (int k = 0; k < 64; k++) sacc += r[k] * sw[k * NC + j];
        g_h2[(size_t)n * NCP + j] = sacc;
        as += sacc * ss[j];
        ad += sacc * sd[j];
    }
    g_as2[n] = as;
    g_ad2[n] = ad;
}

// ---------------- edge passes layer 2 (H=1, C=30; store model) -------------
__global__ void k_esum2(const int* __restrict__ ei, int E, int Etot) {
    int e = blockIdx.x * blockDim.x + threadIdx.x;
    if (e >= Etot) return;
    int s, d; edge_sd(ei, E, e, s, d);
    float v = g_as2[s] + g_ad2[d];
    v = (v > 0.f) ? v : 0.2f * v;
    float ev = __expf(v);
    g_eb2[e] = ev;
    atomicAdd(&g_sum2[d], ev);
}

__global__ void k_emsg2(const int* __restrict__ ei, int E, int Etot,
                        float* __restrict__ a2out) {
    int e = blockIdx.x * blockDim.x + threadIdx.x;
    if (e >= Etot) return;
    int s, d; edge_sd(ei, E, e, s, d);
    float alpha = g_eb2[e] / (g_sum2[d] + 1e-16f);
    if (a2out) a2out[e] = alpha;
    const float4* hp = (const float4*)&g_h2[(size_t)s * NCP];
    float* op = &g_out2[(size_t)d * NCP];
#pragma unroll
    for (int q = 0; q < 7; q++) {
        float4 vv = hp[q];
        red_add_v4(op + q * 4, vv.x * alpha, vv.y * alpha, vv.z * alpha, vv.w * alpha);
    }
    float2 t = *(const float2*)&g_h2[(size_t)s * NCP + 28];
    red_add_v2(op + 28, t.x * alpha, t.y * alpha);
}

// ---------------- final: elu(out2 + b2), log_softmax (float4 loads) --------
__global__ void k_final(const float* __restrict__ b2, float* __restrict__ out) {
    int n = blockIdx.x * blockDim.x + threadIdx.x;
    if (n >= NN) return;
    float v[NC];
    const float4* row = (const float4*)&g_out2[(size_t)n * NCP];
    float m = -INFINITY;
#pragma unroll
    for (int qi = 0; qi < 8; qi++) {
        float4 w = row[qi];
        int base = qi * 4;
        float tv[4] = {w.x, w.y, w.z, w.w};
#pragma unroll
        for (int j = 0; j < 4; j++) {
            int c = base + j;
            if (c < NC) {
                float t = tv[j] + __ldg(&b2[c]);
                t = (t > 0.f) ? t : expm1f(t);
                v[c] = t;
                m = fmaxf(m, t);
            }
        }
    }
    float ssum = 0.f;
#pragma unroll
    for (int c = 0; c < NC; c++) ssum += expf(v[c] - m);
    float lse = m + logf(ssum);
#pragma unroll
    for (int c = 0; c < NC; c++) out[(size_t)n * NC + c] = v[c] - lse;
}

// ---------------- launch ----------------
extern "C" void kernel_launch(void* const* d_in, const int* in_sizes, int n_in,
                              void* d_out, int out_size) {
    const float* x      = (const float*)d_in[0];
    const int*   ei     = (const int*)d_in[1];
    const float* w_res  = (const float*)d_in[2];
    const float* b_res  = (const float*)d_in[3];
    const float* w1     = (const float*)d_in[4];
    const float* att_s1 = (const float*)d_in[5];
    const float* att_d1 = (const float*)d_in[6];
    const float* b1     = (const float*)d_in[7];
    const float* w2     = (const float*)d_in[8];
    const float* att_s2 = (const float*)d_in[9];
    const float* att_d2 = (const float*)d_in[10];
    const float* b2     = (const float*)d_in[11];

    int E = in_sizes[1] / 2;
    int Etot = E + NN;

    float* out = (float*)d_out;
    long long need = (long long)NN * NC + (long long)Etot * HEADS + (long long)Etot;
    float *a1out = nullptr, *a2out = nullptr;
    if ((long long)out_size >= need) {
        a1out = out + (size_t)NN * NC;
        a2out = a1out + (size_t)Etot * HEADS;
    }

    // launch order keeps k_emsg1 as the 4th launch for ncu capture
    k_initprep<<<(NN * D1 / 4 + 255) / 256, 256>>>(w1, w_res);
    k_gemm1<<<(NN + 127) / 128, 256>>>(x, b_res, att_s1, att_d1);

    k_esum1<<<(Etot + 255) / 256, 256>>>(ei, E, Etot);
    k_emsg1<<<(Etot + 255) / 256, 256>>>(ei, E, Etot, a1out);

    k_gemm2<<<(NN + 127) / 128, 128>>>(w2, att_s2, att_d2, b1);

    k_esum2<<<(Etot + 255) / 256, 256>>>(ei, E, Etot);
    k_emsg2<<<(Etot + 255) / 256, 256>>>(ei, E, Etot, a2out);

    k_final<<<(NN + 127) / 128, 128>>>(b2, out);
}

// round 17
// speedup vs baseline: 1.2330x; 1.0370x over previous
#include <cuda_runtime.h>
#include <cuda_bf16.h>
#include <math.h>
#include <stdint.h>

#define NN    50000
#define NF    2000
#define KPAD  2048
#define D1    64
#define HEADS 8
#define HID   8
#define NC    30
#define NCP   32
#define MAXET 1700000

// ---------------- scratch ----------------
__device__ float g_h1[(size_t)NN * D1];
__device__ float g_res[(size_t)NN * D1];
__device__ float g_as1[NN * HEADS];
__device__ float g_ad1[NN * HEADS];
__device__ float g_sum1[NN * HEADS];
__device__ float g_eb1[(size_t)MAXET * HEADS];
__device__ float g_out1[(size_t)NN * D1];
__device__ float g_h2[(size_t)NN * NCP];
__device__ float g_as2[NN];
__device__ float g_ad2[NN];
__device__ float g_sum2[NN];
__device__ float g_eb2[MAXET];
__device__ float g_out2[(size_t)NN * NCP];
__device__ unsigned short g_wt_hi[128 * KPAD];
__device__ unsigned short g_wt_lo[128 * KPAD];
// CSR (dest-sorted edge ids)
__device__ unsigned g_cnt[NN];
__device__ unsigned g_off[NN];
__device__ unsigned g_pos[NN];
__device__ int      g_csr[MAXET];

// ---------------- helpers ----------------
__device__ __forceinline__ void edge_sd(const int* __restrict__ ei, int E, int e,
                                        int& s, int& d) {
    if (e < E) { s = ei[e]; d = ei[E + e]; }
    else       { s = e - E; d = e - E; }
}
__device__ __forceinline__ void red_add_v4(float* addr, float a, float b, float c, float d) {
    asm volatile("red.global.add.v4.f32 [%0], {%1,%2,%3,%4};"
                 :: "l"(addr), "f"(a), "f"(b), "f"(c), "f"(d) : "memory");
}
__device__ __forceinline__ uint32_t smem_u32(const void* p) {
    uint32_t a;
    asm("{ .reg .u64 t; cvta.to.shared.u64 t, %1; cvt.u32.u64 %0, t; }" : "=r"(a) : "l"(p));
    return a;
}
__device__ __forceinline__ uint32_t pack_bf16x2(float h, float l) {
    uint32_t r;
    asm("cvt.rn.bf16x2.f32 %0, %1, %2;" : "=r"(r) : "f"(h), "f"(l));
    return r;
}
__device__ __forceinline__ void ldsm4(uint32_t& r0, uint32_t& r1, uint32_t& r2,
                                      uint32_t& r3, uint32_t addr) {
    asm volatile("ldmatrix.sync.aligned.m8n8.x4.shared.b16 {%0,%1,%2,%3}, [%4];"
                 : "=r"(r0), "=r"(r1), "=r"(r2), "=r"(r3) : "r"(addr));
}
__device__ __forceinline__ void mma16816(float* d, uint32_t a0, uint32_t a1,
                                         uint32_t a2, uint32_t a3,
                                         uint32_t b0, uint32_t b1) {
    asm volatile("mma.sync.aligned.m16n8k16.row.col.f32.bf16.bf16.f32 "
                 "{%0,%1,%2,%3}, {%4,%5,%6,%7}, {%8,%9}, {%0,%1,%2,%3};"
                 : "+f"(d[0]), "+f"(d[1]), "+f"(d[2]), "+f"(d[3])
                 : "r"(a0), "r"(a1), "r"(a2), "r"(a3), "r"(b0), "r"(b1));
}
__device__ __forceinline__ void cp16(uint32_t smaddr, const void* gptr) {
    asm volatile("cp.async.cg.shared.global [%0], [%1], 16;"
                 :: "r"(smaddr), "l"(gptr) : "memory");
}
__device__ __forceinline__ void cvt_split(float2 v, uint32_t& hi, uint32_t& lo) {
    uint32_t vx = __float_as_uint(v.x), vy = __float_as_uint(v.y);
    hi = __byte_perm(vx, vy, 0x7632);
    float hx = __uint_as_float(vx & 0xFFFF0000u);
    float hy = __uint_as_float(vy & 0xFFFF0000u);
    lo = pack_bf16x2(v.y - hy, v.x - hx);
}

// ---------------- fused init + weight prep ----------------
__global__ void k_initprep(const float* __restrict__ w1, const float* __restrict__ wres) {
    int i = blockIdx.x * blockDim.x + threadIdx.x;
    if (i < 128 * KPAD) {
        int n = i >> 11;
        int k = i & (KPAD - 1);
        float v = 0.f;
        if (k < NF) v = (n < 64) ? w1[(size_t)k * 64 + n] : wres[(size_t)k * 64 + (n - 64)];
        __nv_bfloat16 hi = __float2bfloat16(v);
        float rem = v - __bfloat162float(hi);
        __nv_bfloat16 lo = __float2bfloat16(rem);
        g_wt_hi[i] = __bfloat16_as_ushort(hi);
        g_wt_lo[i] = __bfloat16_as_ushort(lo);
    }
    float4 z = make_float4(0.f, 0.f, 0.f, 0.f);
    if (i < NN * HEADS / 4) ((float4*)g_sum1)[i] = z;
    if (i < NN / 4)         ((float4*)g_sum2)[i] = z;
    if (i < NN)             g_cnt[i] = 0u;
}

// ---------------- CSR build: histogram -> scan -> scatter ------------------
__global__ void k_hist(const int* __restrict__ ei, int E, int Etot) {
    int e = blockIdx.x * blockDim.x + threadIdx.x;
    if (e >= Etot) return;
    int d = (e < E) ? ei[E + e] : (e - E);
    atomicAdd(&g_cnt[d], 1u);
}

__global__ __launch_bounds__(1024) void k_scan() {   // single block
    __shared__ unsigned ssum[1024];
    const int t = threadIdx.x;
    const int CH = (NN + 1023) / 1024;   // 49
    int lo = t * CH, hi = lo + CH; if (hi > NN) hi = NN;
    unsigned s = 0;
    for (int i = lo; i < hi; i++) s += g_cnt[i];
    ssum[t] = s;
    __syncthreads();
    for (int ofs = 1; ofs < 1024; ofs <<= 1) {
        unsigned v = (t >= ofs) ? ssum[t - ofs] : 0u;
        __syncthreads();
        ssum[t] += v;
        __syncthreads();
    }
    unsigned base = (t == 0) ? 0u : ssum[t - 1];
    for (int i = lo; i < hi; i++) {
        unsigned c = g_cnt[i];
        g_off[i] = base;
        g_pos[i] = base;
        base += c;
    }
}

__global__ void k_scatter(const int* __restrict__ ei, int E, int Etot) {
    int e = blockIdx.x * blockDim.x + threadIdx.x;
    if (e >= Etot) return;
    int d = (e < E) ? ei[E + e] : (e - E);
    unsigned p = atomicAdd(&g_pos[d], 1u);
    g_csr[p] = e;
}

// ---------------- GEMM1 via mma.sync bf16x3 + fused att1 (R16, proven) -----
#define NCH 63

__global__ __launch_bounds__(256, 2) void k_gemm1(const float* __restrict__ x,
                                                  const float* __restrict__ bres,
                                                  const float* __restrict__ asrc,
                                                  const float* __restrict__ adst) {
    __shared__ __align__(1024) unsigned char Bsm[32768];

    const int tid = threadIdx.x, wid = tid >> 5, lane = tid & 31;
    const int g = lane >> 2, c4 = lane & 3;
    const int mbase = blockIdx.x * 128 + wid * 16;
    int r0 = mbase + g;      if (r0 >= NN) r0 = NN - 1;
    int r1 = mbase + g + 8;  if (r1 >= NN) r1 = NN - 1;
    const uint32_t sb = smem_u32(Bsm);

    const int nL   = (lane & 7) | ((lane & 16) >> 1);
    const int cbit = (lane >> 3) & 1;
    const int q    = cbit ^ ((nL >> 1) & 3);
    const uint32_t lrow = (uint32_t)(nL * 64);

    const int fn0 = tid >> 2, fc0 = tid & 3;
    const int fn1 = (tid + 256) >> 2, fc1 = (tid + 256) & 3;
    const uint32_t fd0 = (uint32_t)(fn0 * 64 + ((fc0 ^ ((fn0 >> 1) & 3)) << 4));
    const uint32_t fd1 = (uint32_t)(fn1 * 64 + ((fc1 ^ ((fn1 >> 1) & 3)) << 4));

    float acc[16][4];
#pragma unroll
    for (int i = 0; i < 16; i++)
#pragma unroll
        for (int j = 0; j < 4; j++) acc[i][j] = 0.f;

    {
        const char* sh0 = (const char*)&g_wt_hi[(size_t)fn0 * KPAD + fc0 * 8];
        const char* sh1 = (const char*)&g_wt_hi[(size_t)fn1 * KPAD + fc1 * 8];
        const char* sl0 = (const char*)&g_wt_lo[(size_t)fn0 * KPAD + fc0 * 8];
        const char* sl1 = (const char*)&g_wt_lo[(size_t)fn1 * KPAD + fc1 * 8];
        cp16(sb + fd0, sh0);             cp16(sb + fd1, sh1);
        cp16(sb + 16384 + fd0, sl0);     cp16(sb + 16384 + fd1, sl1);
        asm volatile("cp.async.commit_group;");
        asm volatile("cp.async.wait_group 0;");
    }
    __syncthreads();

    const int kc = 2 * c4;
    float2 abuf[2][4];
#pragma unroll
    for (int t0 = 0; t0 < 2; t0++) {
        int col = t0 * 16 + kc;
        abuf[t0][0] = *(const float2*)&x[(size_t)r0 * NF + col];
        abuf[t0][1] = *(const float2*)&x[(size_t)r1 * NF + col];
        abuf[t0][2] = *(const float2*)&x[(size_t)r0 * NF + col + 8];
        abuf[t0][3] = *(const float2*)&x[(size_t)r1 * NF + col + 8];
    }

    for (int c = 0; c < NCH; c++) {
        const uint32_t buf = (uint32_t)(c & 1) * 8192u;
        if (c + 1 < NCH) {
            const uint32_t nbuf = (uint32_t)((c + 1) & 1) * 8192u;
            size_t koff = (size_t)(c + 1) * 32;
            const char* sh0 = (const char*)&g_wt_hi[(size_t)fn0 * KPAD + koff + fc0 * 8];
            const char* sh1 = (const char*)&g_wt_hi[(size_t)fn1 * KPAD + koff + fc1 * 8];
            const char* sl0 = (const char*)&g_wt_lo[(size_t)fn0 * KPAD + koff + fc0 * 8];
            const char* sl1 = (const char*)&g_wt_lo[(size_t)fn1 * KPAD + koff + fc1 * 8];
            cp16(sb + nbuf + fd0, sh0);          cp16(sb + nbuf + fd1, sh1);
            cp16(sb + 16384 + nbuf + fd0, sl0);  cp16(sb + 16384 + nbuf + fd1, sl1);
            asm volatile("cp.async.commit_group;");
        }
#pragma unroll
        for (int s = 0; s < 2; s++) {
            const int t = c * 2 + s;
            const int slot = t & 1;
            uint32_t ah[4], al[4];
#pragma unroll
            for (int i = 0; i < 4; i++) cvt_split(abuf[slot][i], ah[i], al[i]);
            {
                int ncol = (t + 2) * 16 + kc;
                bool p0 = ncol < NF, p1 = (ncol + 8) < NF;
                abuf[slot][0] = p0 ? *(const float2*)&x[(size_t)r0 * NF + ncol] : make_float2(0.f, 0.f);
                abuf[slot][1] = p0 ? *(const float2*)&x[(size_t)r1 * NF + ncol] : make_float2(0.f, 0.f);
                abuf[slot][2] = p1 ? *(const float2*)&x[(size_t)r0 * NF + ncol + 8] : make_float2(0.f, 0.f);
                abuf[slot][3] = p1 ? *(const float2*)&x[(size_t)r1 * NF + ncol + 8] : make_float2(0.f, 0.f);
            }

            const uint32_t loff = lrow + ((uint32_t)(q ^ (s << 1)) << 4);
            uint32_t bh[2][4];
            {
                uint32_t a0 = sb + buf + loff;
                ldsm4(bh[0][0], bh[0][1], bh[0][2], bh[0][3], a0);
            }
#pragma unroll
            for (int nb = 0; nb < 8; nb++) {
                const int cur = nb & 1, nxt = cur ^ 1;
                uint32_t bl0, bl1, bl2, bl3;
                ldsm4(bl0, bl1, bl2, bl3,
                      sb + buf + (uint32_t)(nb * 1024) + loff + 16384u);
                if (nb < 7) {
                    uint32_t an = sb + buf + (uint32_t)((nb + 1) * 1024) + loff;
                    ldsm4(bh[nxt][0], bh[nxt][1], bh[nxt][2], bh[nxt][3], an);
                }
                float* d0 = acc[nb * 2];
                float* d1 = acc[nb * 2 + 1];
                mma16816(d0, ah[0], ah[1], ah[2], ah[3], bh[cur][0], bh[cur][1]);
                mma16816(d0, al[0], al[1], al[2], al[3], bh[cur][0], bh[cur][1]);
                mma16816(d1, ah[0], ah[1], ah[2], ah[3], bh[cur][2], bh[cur][3]);
                mma16816(d1, al[0], al[1], al[2], al[3], bh[cur][2], bh[cur][3]);
                mma16816(d0, ah[0], ah[1], ah[2], ah[3], bl0, bl1);
                mma16816(d1, ah[0], ah[1], ah[2], ah[3], bl2, bl3);
            }
        }
        if (c + 1 < NCH) {
            asm volatile("cp.async.wait_group 0;");
            __syncthreads();
        }
    }

    int row0 = mbase + g, row1 = mbase + g + 8;
#pragma unroll
    for (int nf = 0; nf < 16; nf++) {
        int col = nf * 8 + 2 * c4;
        float2 v0 = make_float2(acc[nf][0], acc[nf][1]);
        float2 v1 = make_float2(acc[nf][2], acc[nf][3]);
        if (col < 64) {
            if (row0 < NN) *(float2*)&g_h1[(size_t)row0 * 64 + col] = v0;
            if (row1 < NN) *(float2*)&g_h1[(size_t)row1 * 64 + col] = v1;
        } else {
            int nr = col - 64;
            float b0 = __ldg(&bres[nr]), b1 = __ldg(&bres[nr + 1]);
            v0.x += b0; v0.y += b1; v1.x += b0; v1.y += b1;
            if (row0 < NN) *(float2*)&g_res[(size_t)row0 * 64 + nr] = v0;
            if (row1 < NN) *(float2*)&g_res[(size_t)row1 * 64 + nr] = v1;
        }
    }

#pragma unroll
    for (int nf = 0; nf < 8; nf++) {
        float ws0 = __ldg(&asrc[nf * 8 + 2 * c4]);
        float ws1 = __ldg(&asrc[nf * 8 + 2 * c4 + 1]);
        float wd0 = __ldg(&adst[nf * 8 + 2 * c4]);
        float wd1 = __ldg(&adst[nf * 8 + 2 * c4 + 1]);
        float ps0 = acc[nf][0] * ws0 + acc[nf][1] * ws1;
        float pd0 = acc[nf][0] * wd0 + acc[nf][1] * wd1;
        float ps1 = acc[nf][2] * ws0 + acc[nf][3] * ws1;
        float pd1 = acc[nf][2] * wd0 + acc[nf][3] * wd1;
        ps0 += __shfl_xor_sync(0xffffffffu, ps0, 1);
        ps0 += __shfl_xor_sync(0xffffffffu, ps0, 2);
        pd0 += __shfl_xor_sync(0xffffffffu, pd0, 1);
        pd0 += __shfl_xor_sync(0xffffffffu, pd0, 2);
        ps1 += __shfl_xor_sync(0xffffffffu, ps1, 1);
        ps1 += __shfl_xor_sync(0xffffffffu, ps1, 2);
        pd1 += __shfl_xor_sync(0xffffffffu, pd1, 1);
        pd1 += __shfl_xor_sync(0xffffffffu, pd1, 2);
        if (c4 == 0) {
            if (row0 < NN) { g_as1[row0 * 8 + nf] = ps0; g_ad1[row0 * 8 + nf] = pd0; }
            if (row1 < NN) { g_as1[row1 * 8 + nf] = ps1; g_ad1[row1 * 8 + nf] = pd1; }
        }
    }
}

// ---------------- edge pass 1a: exp + store + sum (unchanged) --------------
__global__ void k_esum1(const int* __restrict__ ei, int E, int Etot) {
    int e = blockIdx.x * blockDim.x + threadIdx.x;
    if (e >= Etot) return;
    int s, d; edge_sd(ei, E, e, s, d);
    float4 s0 = *(const float4*)&g_as1[s * 8];
    float4 s1 = *(const float4*)&g_as1[s * 8 + 4];
    float4 d0 = *(const float4*)&g_ad1[d * 8];
    float4 d1 = *(const float4*)&g_ad1[d * 8 + 4];
    float v[8] = {s0.x + d0.x, s0.y + d0.y, s0.z + d0.z, s0.w + d0.w,
                  s1.x + d1.x, s1.y + d1.y, s1.z + d1.z, s1.w + d1.w};
    float ev[8];
#pragma unroll
    for (int h = 0; h < 8; h++) {
        float t = (v[h] > 0.f) ? v[h] : 0.2f * v[h];
        ev[h] = __expf(t);
    }
    *(float4*)&g_eb1[(size_t)e * 8]     = make_float4(ev[0], ev[1], ev[2], ev[3]);
    *(float4*)&g_eb1[(size_t)e * 8 + 4] = make_float4(ev[4], ev[5], ev[6], ev[7]);
    red_add_v4(&g_sum1[d * 8],     ev[0], ev[1], ev[2], ev[3]);
    red_add_v4(&g_sum1[d * 8 + 4], ev[4], ev[5], ev[6], ev[7]);
}

// ---------------- layer-1 message GATHER: warp per dest node ---------------
__global__ __launch_bounds__(256) void k_emsg1_csr(const int* __restrict__ ei, int E,
                                                   float* __restrict__ a1out) {
    int warp = (blockIdx.x * blockDim.x + threadIdx.x) >> 5;
    int l = threadIdx.x & 31;
    if (warp >= NN) return;
    const int d = warp;
    const unsigned off = g_off[d], cnt = g_cnt[d];
    const int head = l >> 2;
    const float qv = g_sum1[d * 8 + head] + 1e-16f;
    float2 acc = make_float2(0.f, 0.f);
    int e = g_csr[off];            // cnt >= 1 always (self loop)
    for (unsigned i = 0; i < cnt; i++) {
        int en = (i + 1 < cnt) ? g_csr[off + i + 1] : 0;
        int s = (e < E) ? __ldg(&ei[e]) : (e - E);
        float ev = g_eb1[(size_t)e * 8 + head];
        float alpha = ev / qv;
        if (a1out && (l & 3) == 0) a1out[(size_t)e * 8 + head] = alpha;
        float2 hv = *(const float2*)&g_h1[(size_t)s * 64 + 2 * l];
        acc.x += alpha * hv.x;
        acc.y += alpha * hv.y;
        e = en;
    }
    *(float2*)&g_out1[(size_t)d * 64 + 2 * l] = acc;
}

// ---------------- GEMM2 (+ fused x1 elu) + att2 coefficients ---------------
__global__ __launch_bounds__(128) void k_gemm2(const float* __restrict__ w2,
                                               const float* __restrict__ watt_s,
                                               const float* __restrict__ watt_d,
                                               const float* __restrict__ b1) {
    __shared__ float sw[64 * NC];
    __shared__ float ss[NC], sd[NC];
    __shared__ float sb1[64];
    int tid = threadIdx.x;
    for (int i = tid; i < 64 * NC; i += blockDim.x) sw[i] = w2[i];
    if (tid < NC) { ss[tid] = watt_s[tid]; sd[tid] = watt_d[tid]; }
    if (tid < 64) sb1[tid] = b1[tid];
    __syncthreads();
    int n = blockIdx.x * blockDim.x + tid;
    if (n >= NN) return;
    float r[64];
    const float4* orow = (const float4*)&g_out1[(size_t)n * 64];
    const float4* rrow = (const float4*)&g_res[(size_t)n * 64];
#pragma unroll
    for (int i = 0; i < 16; i++) {
        float4 o = orow[i];
        float4 rr = rrow[i];
        float t0 = o.x + sb1[i * 4 + 0] + rr.x;
        float t1 = o.y + sb1[i * 4 + 1] + rr.y;
        float t2 = o.z + sb1[i * 4 + 2] + rr.z;
        float t3 = o.w + sb1[i * 4 + 3] + rr.w;
        r[i * 4 + 0] = (t0 > 0.f) ? t0 : expm1f(t0);
        r[i * 4 + 1] = (t1 > 0.f) ? t1 : expm1f(t1);
        r[i * 4 + 2] = (t2 > 0.f) ? t2 : expm1f(t2);
        r[i * 4 + 3] = (t3 > 0.f) ? t3 : expm1f(t3);
    }
    float as = 0.f, ad = 0.f;
#pragma unroll
    for (int j = 0; j < NC; j++) {
        float sacc = 0.f;
#pragma unroll
        for (int k = 0; k < 64; k++) sacc += r[k] * sw[k * NC + j];
        g_h2[(size_t)n * NCP + j] = sacc;
        as += sacc * ss[j];
        ad += sacc * sd[j];
    }
    g_h2[(size_t)n * NCP + 30] = 0.f;   // zero padding cols (read by gather)
    g_h2[(size_t)n * NCP + 31] = 0.f;
    g_as2[n] = as;
    g_ad2[n] = ad;
}

// ---------------- edge pass 2a: exp + store + sum (unchanged) --------------
__global__ void k_esum2(const int* __restrict__ ei, int E, int Etot) {
    int e = blockIdx.x * blockDim.x + threadIdx.x;
    if (e >= Etot) return;
    int s, d; edge_sd(ei, E, e, s, d);
    float v = g_as2[s] + g_ad2[d];
    v = (v > 0.f) ? v : 0.2f * v;
    float ev = __expf(v);
    g_eb2[e] = ev;
    atomicAdd(&g_sum2[d], ev);
}

// ---------------- layer-2 message GATHER: warp per dest node ---------------
__global__ __launch_bounds__(256) void k_emsg2_csr(const int* __restrict__ ei, int E,
                                                   float* __restrict__ a2out) {
    int warp = (blockIdx.x * blockDim.x + threadIdx.x) >> 5;
    int l = threadIdx.x & 31;
    if (warp >= NN) return;
    const int d = warp;
    const unsigned off = g_off[d], cnt = g_cnt[d];
    const float qv = g_sum2[d] + 1e-16f;
    float acc = 0.f;
    int e = g_csr[off];
    for (unsigned i = 0; i < cnt; i++) {
        int en = (i + 1 < cnt) ? g_csr[off + i + 1] : 0;
        int s = (e < E) ? __ldg(&ei[e]) : (e - E);
        float alpha = g_eb2[e] / qv;
        if (a2out && l == 0) a2out[e] = alpha;
        float hv = g_h2[(size_t)s * NCP + l];
        acc += alpha * hv;
        e = en;
    }
    g_out2[(size_t)d * NCP + l] = acc;
}

// ---------------- final: elu(out2 + b2), log_softmax ----------------
__global__ void k_final(const float* __restrict__ b2, float* __restrict__ out) {
    int n = blockIdx.x * blockDim.x + threadIdx.x;
    if (n >= NN) return;
    float v[NC];
    const float4* row = (const float4*)&g_out2[(size_t)n * NCP];
    float m = -INFINITY;
#pragma unroll
    for (int qi = 0; qi < 8; qi++) {
        float4 w = row[qi];
        int base = qi * 4;
        float tv[4] = {w.x, w.y, w.z, w.w};
#pragma unroll
        for (int j = 0; j < 4; j++) {
            int c = base + j;
            if (c < NC) {
                float t = tv[j] + __ldg(&b2[c]);
                t = (t > 0.f) ? t : expm1f(t);
                v[c] = t;
                m = fmaxf(m, t);
            }
        }
    }
    float ssum = 0.f;
#pragma unroll
    for (int c = 0; c < NC; c++) ssum += expf(v[c] - m);
    float lse = m + logf(ssum);
#pragma unroll
    for (int c = 0; c < NC; c++) out[(size_t)n * NC + c] = v[c] - lse;
}

// ---------------- launch ----------------
extern "C" void kernel_launch(void* const* d_in, const int* in_sizes, int n_in,
                              void* d_out, int out_size) {
    const float* x      = (const float*)d_in[0];
    const int*   ei     = (const int*)d_in[1];
    const float* w_res  = (const float*)d_in[2];
    const float* b_res  = (const float*)d_in[3];
    const float* w1     = (const float*)d_in[4];
    const float* att_s1 = (const float*)d_in[5];
    const float* att_d1 = (const float*)d_in[6];
    const float* b1     = (const float*)d_in[7];
    const float* w2     = (const float*)d_in[8];
    const float* att_s2 = (const float*)d_in[9];
    const float* att_d2 = (const float*)d_in[10];
    const float* b2     = (const float*)d_in[11];

    int E = in_sizes[1] / 2;
    int Etot = E + NN;

    float* out = (float*)d_out;
    long long need = (long long)NN * NC + (long long)Etot * HEADS + (long long)Etot;
    float *a1out = nullptr, *a2out = nullptr;
    if ((long long)out_size >= need) {
        a1out = out + (size_t)NN * NC;
        a2out = a1out + (size_t)Etot * HEADS;
    }

    k_initprep<<<(NN * D1 / 4 + 255) / 256, 256>>>(w1, w_res);
    k_hist<<<(Etot + 255) / 256, 256>>>(ei, E, Etot);
    k_scan<<<1, 1024>>>();
    k_scatter<<<(Etot + 255) / 256, 256>>>(ei, E, Etot);

    k_gemm1<<<(NN + 127) / 128, 256>>>(x, b_res, att_s1, att_d1);
    k_esum1<<<(Etot + 255) / 256, 256>>>(ei, E, Etot);
    k_emsg1_csr<<<(NN * 32 + 255) / 256, 256>>>(ei, E, a1out);

    k_gemm2<<<(NN + 127) / 128, 128>>>(w2, att_s2, att_d2, b1);
    k_esum2<<<(Etot + 255) / 256, 256>>>(ei, E, Etot);
    k_emsg2_csr<<<(NN * 32 + 255) / 256, 256>>>(ei, E, a2out);

    k_final<<<(NN + 127) / 128, 128>>>(b2, out);
}